// round 3
// baseline (speedup 1.0000x reference)
#include <cuda_runtime.h>
#include <math.h>

#define B   512
#define TP  256
#define TFD 64
#define DF  64
#define DS  32
#define DM  512
#define NE  6
#define NPAIR 532   // 4*6 + 508
#define MB  16      // samples per k_base tile
#define TILES 33

typedef unsigned long long u64;

// ---------------- device scratch ----------------
__device__ float g_ab[1000];
__device__ float g_gctx[B*DM];
__device__ float g_temb[B*DM];
__device__ float g_probs[B*NE];
__device__ int   g_sel[B];
__device__ float g_loss[B];
__device__ float g_outsub[NE*4*TFD*DF];
__device__ int   g_cnt[NE];
__device__ int   g_listE[NE*544];
__device__ float g_base[NE*B*512];   // 6.29 MB

// ---------------- f32x2 helpers ----------------
__device__ __forceinline__ void ffma2(u64 &d, u64 a, u64 b){
    asm("fma.rn.f32x2 %0, %1, %2, %0;" : "+l"(d) : "l"(a), "l"(b));
}
__device__ __forceinline__ u64 pack2(float lo, float hi){
    u64 r; asm("mov.b64 %0, {%1,%2};" : "=l"(r) : "f"(lo), "f"(hi)); return r;
}
__device__ __forceinline__ float2 unpk(u64 v){
    float2 f; f.x = __uint_as_float((unsigned)v); f.y = __uint_as_float((unsigned)(v>>32)); return f;
}

__device__ __forceinline__ float gelu_f(float x){
    float inner = 0.7978845608028654f*(x + 0.044715f*x*x*x);
    return 0.5f*x*(1.0f + tanhf(inner));
}

// ---------------- K0: alphas_bar ----------------
__global__ void k_init(){
    if (threadIdx.x == 0){
        float ab = 1.0f;
        const float step = (0.02f - 0.0001f) / 999.0f;
        for (int i = 0; i < 1000; i++){
            float beta = 0.0001f + step * (float)i;
            ab *= (1.0f - beta);
            g_ab[i] = ab;
        }
    }
}

// ---------------- K1: time embedding ----------------
__global__ void k_temb(const int* __restrict__ t){
    int b = blockIdx.x;
    float tv = (float)t[b];
    for (int j = threadIdx.x; j < DM; j += blockDim.x){
        int i = (j < 256) ? j : (j - 256);
        float freq = expf(-9.210340371976184f * (float)i / 256.0f);
        float a = tv * freq;
        g_temb[b*DM + j] = (j < 256) ? sinf(a) : cosf(a);
    }
}

// ---------------- K2: ctx GEMM + gelu + mean (f32x2) ----------------
__global__ void k_ctx(const float* __restrict__ obs, const float* __restrict__ sc,
                      const float* __restrict__ Wenc, const float* __restrict__ benc,
                      const float* __restrict__ Wstat){
    __shared__ float obs_s[16][64];   // 4KB
    int b = blockIdx.y;
    int j = blockIdx.x*128 + threadIdx.x;
    int tid = threadIdx.x;

    u64 wp[32];
    #pragma unroll
    for (int i = 0; i < 32; i++)
        wp[i] = pack2(Wenc[(2*i)*DM + j], Wenc[(2*i+1)*DM + j]);

    float pre = benc[j];
    #pragma unroll
    for (int k = 0; k < 32; k++) pre = fmaf(sc[b*DS + k], Wstat[k*DM + j], pre);

    float sum = 0.0f;
    const float* ob = obs + (size_t)b*TP*DF;
    for (int tp0 = 0; tp0 < TP; tp0 += 16){
        __syncthreads();
        const float4* src = (const float4*)(ob + tp0*DF);
        #pragma unroll
        for (int i = 0; i < 2; i++)
            ((float4*)obs_s)[tid + i*128] = src[tid + i*128];
        __syncthreads();
        #pragma unroll 2
        for (int r = 0; r < 16; r++){
            u64 acc2 = pack2(pre, 0.0f);
            const ulonglong2* xr = (const ulonglong2*)&obs_s[r][0];
            #pragma unroll
            for (int i = 0; i < 16; i++){
                ulonglong2 v = xr[i];
                ffma2(acc2, v.x, wp[2*i]);
                ffma2(acc2, v.y, wp[2*i+1]);
            }
            float2 a = unpk(acc2);
            sum += gelu_f(a.x + a.y);
        }
    }
    g_gctx[b*DM + j] = sum * (1.0f/256.0f);
}

// ---------------- K3: router (64 blocks x 8 warps) ----------------
__global__ void k_router(const float* __restrict__ Wr, const float* __restrict__ br,
                         const int* __restrict__ phase){
    int warp = threadIdx.x >> 5;
    int lane = threadIdx.x & 31;
    int b = blockIdx.x*8 + warp;
    float p[6] = {0,0,0,0,0,0};
    for (int k = lane; k < DM; k += 32){
        float g = g_gctx[b*DM + k];
        const float* w = Wr + k*NE;
        #pragma unroll
        for (int e = 0; e < 6; e++) p[e] = fmaf(g, w[e], p[e]);
    }
    #pragma unroll
    for (int off = 16; off; off >>= 1){
        #pragma unroll
        for (int e = 0; e < 6; e++) p[e] += __shfl_xor_sync(0xffffffff, p[e], off);
    }
    if (lane == 0){
        float l[6], pr[6];
        #pragma unroll
        for (int e = 0; e < 6; e++) l[e] = p[e] + br[e];
        float m = l[0];
        #pragma unroll
        for (int e = 1; e < 6; e++) m = fmaxf(m, l[e]);
        float s = 0.0f;
        #pragma unroll
        for (int e = 0; e < 6; e++){ pr[e] = expf(l[e] - m); s += pr[e]; }
        float inv = 1.0f / s;
        #pragma unroll
        for (int e = 0; e < 6; e++){ pr[e] *= inv; g_probs[b*NE + e] = pr[e]; }
        int pl = phase[b];
        g_sel[b] = pl + ((pr[pl+3] > pr[pl]) ? 3 : 0);
    }
}

// ---------------- K3b: build per-expert sample lists ----------------
__global__ void k_pairs(){
    int tid = threadIdx.x;  // 512
    if (tid < NE) g_cnt[tid] = 0;
    __syncthreads();
    int b = tid;
    if (b < 4){
        #pragma unroll
        for (int e = 0; e < NE; e++){
            int idx = atomicAdd(&g_cnt[e], 1);
            g_listE[e*544 + idx] = b;
        }
    } else {
        int e = g_sel[b];
        int idx = atomicAdd(&g_cnt[e], 1);
        g_listE[e*544 + idx] = b;
    }
}

// ---------------- K3c: base[e][b][h] per-expert GEMM ----------------
// block = (e, tile of 16 samples); 256 threads; K=1024, N=512
__global__ void k_base(const float* __restrict__ W1, const float* __restrict__ b1){
    __shared__ float wsm[16*512];     // 32KB: 16 K-rows x 512 h
    __shared__ u64  adup[16][16];     // duplicated A vals
    __shared__ int  bl[16];

    int e    = blockIdx.x / TILES;
    int tile = blockIdx.x % TILES;
    int n  = g_cnt[e];
    int s0 = tile*MB;
    if (s0 >= n) return;
    int tid = threadIdx.x;

    if (tid < 16){
        int s = s0 + tid;
        bl[tid] = (s < n) ? g_listE[e*544 + s] : g_listE[e*544]; // clamp; duplicate rows benign
    }
    __syncthreads();

    int h0 = (tid & 63) * 8;
    int sg = tid >> 6;          // 0..3, samples sg*4..sg*4+3

    u64 acc[4][4];
    {
        const float2* bp = (const float2*)(b1 + e*512 + h0);
        #pragma unroll
        for (int hp = 0; hp < 4; hp++){
            float2 bb = bp[hp];
            #pragma unroll
            for (int si = 0; si < 4; si++) acc[si][hp] = pack2(bb.x, bb.y);
        }
    }

    const float* W1base = W1 + (size_t)e*1088*512 + 64*512;

    // initial stage (chunk 0)
    {
        const float4* wsrc = (const float4*)W1base;
        #pragma unroll
        for (int i = 0; i < 8; i++)
            ((float4*)wsm)[tid + i*256] = wsrc[tid + i*256];
        int s = tid >> 4, k = tid & 15;
        int bb = bl[s];
        float v = (k < 512) ? g_gctx[bb*512 + k] : g_temb[bb*512 + k - 512]; // k<16 always gctx
        adup[s][k] = pack2(v, v);
    }
    __syncthreads();

    for (int chunk = 0; chunk < 64; chunk++){
        // prefetch next chunk into regs (LDG latency hidden by compute)
        float4 r[8]; float av = 0.0f;
        if (chunk < 63){
            const float4* wsrc = (const float4*)(W1base + (chunk+1)*16*512);
            #pragma unroll
            for (int i = 0; i < 8; i++) r[i] = wsrc[tid + i*256];
            int s = tid >> 4, k = (chunk+1)*16 + (tid & 15);
            int bb = bl[s];
            av = (k < 512) ? g_gctx[bb*512 + k] : g_temb[bb*512 + k - 512];
        }
        // compute
        #pragma unroll 4
        for (int k = 0; k < 16; k++){
            ulonglong2 w01 = *(const ulonglong2*)&wsm[k*512 + h0];
            ulonglong2 w23 = *(const ulonglong2*)&wsm[k*512 + h0 + 4];
            #pragma unroll
            for (int si = 0; si < 4; si++){
                u64 a = adup[sg*4 + si][k];
                ffma2(acc[si][0], a, w01.x);
                ffma2(acc[si][1], a, w01.y);
                ffma2(acc[si][2], a, w23.x);
                ffma2(acc[si][3], a, w23.y);
            }
        }
        __syncthreads();
        if (chunk < 63){
            #pragma unroll
            for (int i = 0; i < 8; i++) ((float4*)wsm)[tid + i*256] = r[i];
            adup[tid >> 4][tid & 15] = pack2(av, av);
        }
        __syncthreads();
    }

    #pragma unroll
    for (int si = 0; si < 4; si++){
        int bb = bl[sg*4 + si];
        float2* dst = (float2*)&g_base[(size_t)(e*B + bb)*512 + h0];
        #pragma unroll
        for (int hp = 0; hp < 4; hp++) dst[hp] = unpk(acc[si][hp]);
    }
}

// ---------------- K4: per-(sample,expert) MLP (f32x2) ----------------
__global__ void k_expert(const float* __restrict__ fut, const float* __restrict__ eps,
                         const int* __restrict__ t,
                         const float* __restrict__ W1, const float* __restrict__ b2_unused,
                         const float* __restrict__ W2, const float* __restrict__ b2){
    extern __shared__ float smf[];
    float* basesm = smf;               // 512
    float* nz     = basesm + 512;      // 4096
    float* hs     = nz + 4096;         // 32*516
    float* w2c    = hs + 32*516;       // 4096
    __shared__ float red[8];

    int p = blockIdx.x;
    int b, e;
    if (p < 24){ b = p / 6; e = p - b*6; }
    else       { b = p - 20; e = g_sel[p - 20]; }
    int tid = threadIdx.x;
    bool do_loss  = (e == g_sel[b]);
    bool do_store = (b < 4);

    float ab = g_ab[t[b]];
    float sa = sqrtf(ab), sb = sqrtf(1.0f - ab);

    for (int i = tid; i < 512; i += 256) basesm[i] = g_base[(size_t)(e*B + b)*512 + i];
    {
        const float* fb = fut + (size_t)b*TFD*DF;
        const float* eb = eps + (size_t)b*TFD*DF;
        for (int i = tid; i < TFD*DF; i += 256) nz[i] = sa*fb[i] + sb*eb[i];
    }
    __syncthreads();

    const float* W1e = W1 + (size_t)e*1088*512;
    const float* W2e = W2 + (size_t)e*512*64;

    float lsum = 0.0f;
    int lf0 = 2*(tid >> 4);
    int f0  = 4*(tid & 15);

    for (int th = 0; th < 2; th++){
        // phase1: hs[tf][h] = gelu(noisy @ W1[:64] + base)  [f32x2 k-packed]
        for (int hc = 0; hc < 2; hc++){
            int h = tid + hc*256;
            u64 wa2[32];
            #pragma unroll
            for (int i = 0; i < 32; i++)
                wa2[i] = pack2(W1e[(2*i)*512 + h], W1e[(2*i+1)*512 + h]);
            float bh = basesm[h];
            #pragma unroll 2
            for (int tf = 0; tf < 32; tf++){
                const ulonglong2* x2 = (const ulonglong2*)&nz[(th*32 + tf)*64];
                u64 acc2 = pack2(bh, 0.0f);
                #pragma unroll
                for (int i = 0; i < 16; i++){
                    ulonglong2 v = x2[i];
                    ffma2(acc2, v.x, wa2[2*i]);
                    ffma2(acc2, v.y, wa2[2*i+1]);
                }
                float2 ar = unpk(acc2);
                hs[tf*516 + h] = gelu_f(ar.x + ar.y);
            }
        }
        __syncthreads();

        // phase2: out = hs @ W2  [f32x2 f-packed]
        u64 acc2[2][2];
        acc2[0][0]=0ull; acc2[0][1]=0ull; acc2[1][0]=0ull; acc2[1][1]=0ull;

        for (int ch = 0; ch < 8; ch++){
            for (int i = tid; i < 4096; i += 256) w2c[i] = W2e[ch*4096 + i];
            __syncthreads();
            #pragma unroll 4
            for (int hh = 0; hh < 64; hh++){
                float a0 = hs[ lf0     *516 + ch*64 + hh];
                float a1 = hs[(lf0 + 1)*516 + ch*64 + hh];
                u64 a0d = pack2(a0, a0);
                u64 a1d = pack2(a1, a1);
                ulonglong2 w = *(const ulonglong2*)&w2c[hh*64 + f0];
                ffma2(acc2[0][0], a0d, w.x);
                ffma2(acc2[0][1], a0d, w.y);
                ffma2(acc2[1][0], a1d, w.x);
                ffma2(acc2[1][1], a1d, w.y);
            }
            __syncthreads();
        }

        #pragma unroll
        for (int i2 = 0; i2 < 2; i2++){
            int tfg = th*32 + lf0 + i2;
            #pragma unroll
            for (int jj = 0; jj < 2; jj++){
                float2 o2 = unpk(acc2[i2][jj]);
                float oa = o2.x + b2[e*64 + f0 + 2*jj];
                float ob = o2.y + b2[e*64 + f0 + 2*jj + 1];
                if (do_store){
                    g_outsub[(((e*4 + b)*TFD) + tfg)*DF + f0 + 2*jj    ] = oa;
                    g_outsub[(((e*4 + b)*TFD) + tfg)*DF + f0 + 2*jj + 1] = ob;
                }
                if (do_loss){
                    float da = oa - eps[(size_t)b*4096 + tfg*64 + f0 + 2*jj];
                    float db = ob - eps[(size_t)b*4096 + tfg*64 + f0 + 2*jj + 1];
                    lsum += da*da + db*db;
                }
            }
        }
        __syncthreads();
    }

    if (do_loss){
        #pragma unroll
        for (int off = 16; off; off >>= 1) lsum += __shfl_xor_sync(0xffffffff, lsum, off);
        if ((tid & 31) == 0) red[tid >> 5] = lsum;
        __syncthreads();
        if (tid == 0){
            float tot = 0.0f;
            #pragma unroll
            for (int w = 0; w < 8; w++) tot += red[w];
            g_loss[b] = tot * (1.0f/4096.0f);
        }
    }
}

// ---------------- K5: final scalar ----------------
__global__ void k_final(float* __restrict__ out){
    __shared__ float s_lossw, s_chain, s_smooth;
    __shared__ float s_psum[6];
    __shared__ int   s_cnt[6];
    int tid = threadIdx.x;
    if (tid == 0){ s_lossw = 0.0f; s_chain = 0.0f; s_smooth = 0.0f; }
    if (tid < 6){ s_psum[tid] = 0.0f; s_cnt[tid] = 0; }
    __syncthreads();

    const float PW[3] = {1.0f, 5.0f, 5.0f};
    float lw = 0.0f, lp[6] = {0,0,0,0,0,0};
    int   lc[6] = {0,0,0,0,0,0};
    for (int b = tid; b < B; b += 256){
        int s = g_sel[b];
        lw += g_loss[b] * PW[s % 3];
        lc[s]++;
        #pragma unroll
        for (int e = 0; e < 6; e++) lp[e] += g_probs[b*NE + e];
    }
    atomicAdd(&s_lossw, lw);
    #pragma unroll
    for (int e = 0; e < 6; e++){ atomicAdd(&s_psum[e], lp[e]); atomicAdd(&s_cnt[e], lc[e]); }

    const int pa[7] = {0,1,3,4,0,1,2};
    const int pb[7] = {1,2,4,5,3,4,5};
    float ch = 0.0f;
    for (int i = tid; i < 16384; i += 256){
        #pragma unroll
        for (int q = 0; q < 7; q++){
            float d = g_outsub[pa[q]*16384 + i] - g_outsub[pb[q]*16384 + i];
            ch += d*d;
        }
    }
    atomicAdd(&s_chain, ch);

    float smv = 0.0f;
    for (int i = tid; i < 96768; i += 256){
        int e  = i / 16128; int r  = i - e*16128;
        int s  = r / 4032;  int r2 = r - s*4032;
        int idx = (e*4 + s)*4096 + r2;
        float d = g_outsub[idx + 64] - g_outsub[idx];
        smv += d*d;
    }
    atomicAdd(&s_smooth, smv);
    __syncthreads();

    if (tid == 0){
        float lb = 0.0f;
        #pragma unroll
        for (int e = 0; e < 6; e++)
            lb += ((float)s_cnt[e] / 512.0f) * (s_psum[e] / 512.0f);
        float total = s_lossw / 512.0f
                    + 0.01f * (s_chain / 16384.0f + 0.5f * s_smooth / 16128.0f)
                    + 0.06f * lb;
        out[0] = total;
    }
}

// ---------------- launch ----------------
extern "C" void kernel_launch(void* const* d_in, const int* in_sizes, int n_in,
                              void* d_out, int out_size){
    const float* obs  = (const float*)d_in[0];
    const float* fut  = (const float*)d_in[1];
    const float* sc   = (const float*)d_in[2];
    const float* eps  = (const float*)d_in[3];
    const int*   phase= (const int*)  d_in[4];
    const int*   t    = (const int*)  d_in[5];
    const float* Wenc = (const float*)d_in[6];
    const float* benc = (const float*)d_in[7];
    const float* Wstat= (const float*)d_in[8];
    const float* Wr   = (const float*)d_in[9];
    const float* br   = (const float*)d_in[10];
    const float* W1   = (const float*)d_in[11];
    const float* b1   = (const float*)d_in[12];
    const float* W2   = (const float*)d_in[13];
    const float* b2   = (const float*)d_in[14];

    const int SMEM_EXPERT = (512 + 4096 + 32*516 + 4096) * 4; // 100,864 B
    static bool attr_done = false;
    if (!attr_done){
        cudaFuncSetAttribute(k_expert, cudaFuncAttributeMaxDynamicSharedMemorySize, SMEM_EXPERT);
        attr_done = true;
    }

    k_init  <<<1, 32>>>();
    k_temb  <<<B, 256>>>(t);
    k_ctx   <<<dim3(4, B), 128>>>(obs, sc, Wenc, benc, Wstat);
    k_router<<<64, 256>>>(Wr, br, phase);
    k_pairs <<<1, 512>>>();
    k_base  <<<NE*TILES, 256>>>(W1, b1);
    k_expert<<<NPAIR, 256, SMEM_EXPERT>>>(fut, eps, t, W1, b1, W2, b2);
    k_final <<<1, 256>>>((float*)d_out);
}

// round 4
// speedup vs baseline: 1.6548x; 1.6548x over previous
#include <cuda_runtime.h>
#include <cuda_bf16.h>
#include <math.h>

#define B   512
#define TP  256
#define TFD 64
#define DF  64
#define DS  32
#define DM  512
#define NE  6
#define NPAIR 532   // 4*6 + 508

// ---------------- device scratch ----------------
__device__ float g_ab[1000];
__device__ float g_gctx[B*DM];
__device__ float g_temb[B*DM];
__device__ float g_probs[B*NE];
__device__ int   g_sel[B];
__device__ float g_loss[B];
__device__ float g_outsub[NE*4*TFD*DF];

// ---------------- fast gelu: x * sigmoid(2u), u = 0.79788456(x + 0.044715 x^3) ----------------
// identical math to 0.5x(1+tanh(u)); ex2/rcp approx err ~1e-6 rel
__device__ __forceinline__ float gelu_fast(float x){
    float s = x*x;
    float p = x * fmaf(s, 0.044715f, 1.0f);
    float argv = p * -2.3022083f;          // -2*0.79788456*log2(e)
    float e;
    asm("ex2.approx.f32 %0, %1;" : "=f"(e) : "f"(argv));
    float r;
    asm("rcp.approx.f32 %0, %1;" : "=f"(r) : "f"(e + 1.0f));
    return x * r;
}

// ---------------- mma.sync m16n8k16 bf16 ----------------
__device__ __forceinline__ void mma16816(float* c, const unsigned* a, unsigned b0, unsigned b1){
    asm("mma.sync.aligned.m16n8k16.row.col.f32.bf16.bf16.f32 "
        "{%0,%1,%2,%3}, {%4,%5,%6,%7}, {%8,%9}, {%0,%1,%2,%3};"
        : "+f"(c[0]), "+f"(c[1]), "+f"(c[2]), "+f"(c[3])
        : "r"(a[0]), "r"(a[1]), "r"(a[2]), "r"(a[3]), "r"(b0), "r"(b1));
}

// ---------------- K0: alphas_bar ----------------
__global__ void k_init(){
    if (threadIdx.x == 0){
        float ab = 1.0f;
        const float step = (0.02f - 0.0001f) / 999.0f;
        for (int i = 0; i < 1000; i++){
            float beta = 0.0001f + step * (float)i;
            ab *= (1.0f - beta);
            g_ab[i] = ab;
        }
    }
}

// ---------------- K1: time embedding ----------------
__global__ void k_temb(const int* __restrict__ t){
    int b = blockIdx.x;
    float tv = (float)t[b];
    for (int j = threadIdx.x; j < DM; j += blockDim.x){
        int i = (j < 256) ? j : (j - 256);
        float freq = expf(-9.210340371976184f * (float)i / 256.0f);
        float a = tv * freq;
        g_temb[b*DM + j] = (j < 256) ? sinf(a) : cosf(a);
    }
}

// ---------------- K2: ctx GEMM via bf16 tensor cores ----------------
// grid (4 ntiles, 512 b), 512 threads (16 warps). M=256,N=128,K=64 per block.
// smem: As[256][72] bf16 + Bs[128][72] bf16 + pre[128] + colsum[128]
#define APAD 72
__global__ void __launch_bounds__(512, 1)
k_ctx_mma(const float* __restrict__ obs, const float* __restrict__ sc,
          const float* __restrict__ Wenc, const float* __restrict__ benc,
          const float* __restrict__ Wstat){
    extern __shared__ char smraw[];
    __nv_bfloat16* As = (__nv_bfloat16*)smraw;                    // 256*72
    __nv_bfloat16* Bs = As + 256*APAD;                            // 128*72
    float* pre    = (float*)(Bs + 128*APAD);                      // 128
    float* colsum = pre + 128;                                    // 128

    int b  = blockIdx.y;
    int n0 = blockIdx.x * 128;
    int tid = threadIdx.x;

    // --- load obs -> As (bf16, padded) ---
    {
        int row = tid >> 1;
        int c0  = (tid & 1) * 32;
        const float4* src = (const float4*)(obs + (size_t)b*TP*DF + row*64 + c0);
        __nv_bfloat16* arow = As + row*APAD + c0;
        #pragma unroll
        for (int i = 0; i < 8; i++){
            float4 v = src[i];
            __nv_bfloat162 p0 = __floats2bfloat162_rn(v.x, v.y);
            __nv_bfloat162 p1 = __floats2bfloat162_rn(v.z, v.w);
            *(__nv_bfloat162*)(arow + i*4    ) = p0;
            *(__nv_bfloat162*)(arow + i*4 + 2) = p1;
        }
    }
    // --- load Wenc^T -> Bs ---
    {
        int j  = tid >> 2;           // 0..127
        int kq = (tid & 3) * 16;
        int jg = n0 + j;
        #pragma unroll
        for (int i = 0; i < 16; i++)
            Bs[j*APAD + kq + i] = __float2bfloat16_rn(Wenc[(kq + i)*DM + jg]);
    }
    // --- pre[j] = benc + static@Wstat ; zero colsum ---
    if (tid < 128){
        int jg = n0 + tid;
        float acc = benc[jg];
        #pragma unroll
        for (int k = 0; k < 32; k++) acc = fmaf(sc[b*DS + k], Wstat[k*DM + jg], acc);
        pre[tid] = acc;
        colsum[tid] = 0.0f;
    }
    __syncthreads();

    // --- MMA compute: warp tile 32(m) x 64(n) ---
    int warp = tid >> 5, lane = tid & 31;
    int m0 = (warp >> 1) * 32;
    int nb = (warp & 1) * 64;
    int qrow = lane >> 2;
    int qk2  = (lane & 3) * 2;

    float c[2][8][4];
    #pragma unroll
    for (int mt = 0; mt < 2; mt++)
        #pragma unroll
        for (int nt = 0; nt < 8; nt++)
            #pragma unroll
            for (int r = 0; r < 4; r++) c[mt][nt][r] = 0.0f;

    #pragma unroll
    for (int kk = 0; kk < 4; kk++){
        unsigned a[2][4];
        #pragma unroll
        for (int mt = 0; mt < 2; mt++){
            const __nv_bfloat16* ap = As + (m0 + mt*16 + qrow)*APAD + kk*16 + qk2;
            a[mt][0] = *(const unsigned*)(ap);
            a[mt][1] = *(const unsigned*)(ap + 8*APAD);
            a[mt][2] = *(const unsigned*)(ap + 8);
            a[mt][3] = *(const unsigned*)(ap + 8*APAD + 8);
        }
        #pragma unroll
        for (int nt = 0; nt < 8; nt++){
            const __nv_bfloat16* bp = Bs + (nb + nt*8 + qrow)*APAD + kk*16 + qk2;
            unsigned b0 = *(const unsigned*)(bp);
            unsigned b1 = *(const unsigned*)(bp + 8);
            mma16816(c[0][nt], a[0], b0, b1);
            mma16816(c[1][nt], a[1], b0, b1);
        }
    }

    // --- epilogue: +pre, gelu, column sums ---
    #pragma unroll
    for (int nt = 0; nt < 8; nt++){
        int jl = nb + nt*8 + qk2;
        float p0 = pre[jl], p1 = pre[jl + 1];
        float s0 = 0.0f, s1 = 0.0f;
        #pragma unroll
        for (int mt = 0; mt < 2; mt++){
            s0 += gelu_fast(c[mt][nt][0] + p0) + gelu_fast(c[mt][nt][2] + p0);
            s1 += gelu_fast(c[mt][nt][1] + p1) + gelu_fast(c[mt][nt][3] + p1);
        }
        #pragma unroll
        for (int off = 16; off >= 4; off >>= 1){
            s0 += __shfl_xor_sync(0xffffffff, s0, off);
            s1 += __shfl_xor_sync(0xffffffff, s1, off);
        }
        if (qrow == 0){
            atomicAdd(&colsum[jl    ], s0);
            atomicAdd(&colsum[jl + 1], s1);
        }
    }
    __syncthreads();

    if (tid < 128)
        g_gctx[b*DM + n0 + tid] = colsum[tid] * (1.0f/256.0f);
}

// ---------------- K3: router ----------------
__global__ void k_router(const float* __restrict__ Wr, const float* __restrict__ br,
                         const int* __restrict__ phase){
    int warp = threadIdx.x >> 5;
    int lane = threadIdx.x & 31;
    int b = blockIdx.x*8 + warp;
    float p[6] = {0,0,0,0,0,0};
    for (int k = lane; k < DM; k += 32){
        float g = g_gctx[b*DM + k];
        const float* w = Wr + k*NE;
        #pragma unroll
        for (int e = 0; e < 6; e++) p[e] = fmaf(g, w[e], p[e]);
    }
    #pragma unroll
    for (int off = 16; off; off >>= 1){
        #pragma unroll
        for (int e = 0; e < 6; e++) p[e] += __shfl_xor_sync(0xffffffff, p[e], off);
    }
    if (lane == 0){
        float l[6], pr[6];
        #pragma unroll
        for (int e = 0; e < 6; e++) l[e] = p[e] + br[e];
        float m = l[0];
        #pragma unroll
        for (int e = 1; e < 6; e++) m = fmaxf(m, l[e]);
        float s = 0.0f;
        #pragma unroll
        for (int e = 0; e < 6; e++){ pr[e] = expf(l[e] - m); s += pr[e]; }
        float inv = 1.0f / s;
        #pragma unroll
        for (int e = 0; e < 6; e++){ pr[e] *= inv; g_probs[b*NE + e] = pr[e]; }
        int pl = phase[b];
        g_sel[b] = pl + ((pr[pl+3] > pr[pl]) ? 3 : 0);
    }
}

// ---------------- K4: per-(sample,expert) MLP (R2 version, fast gelu) ----------------
__global__ void k_expert(const float* __restrict__ fut, const float* __restrict__ eps,
                         const int* __restrict__ t,
                         const float* __restrict__ W1, const float* __restrict__ b1,
                         const float* __restrict__ W2, const float* __restrict__ b2){
    extern __shared__ float smf[];
    float* gt   = smf;               // 1024
    float* base = gt + 1024;         // 512
    float* nz   = base + 512;        // 4096
    float* hs   = nz + 4096;         // 32*516
    float* w2c  = hs + 32*516;       // 4096
    __shared__ float red[8];

    int p = blockIdx.x;
    int b, e;
    if (p < 24){ b = p / 6; e = p - b*6; }
    else       { b = p - 20; e = g_sel[p - 20]; }
    int tid = threadIdx.x;
    bool do_loss  = (e == g_sel[b]);
    bool do_store = (b < 4);

    float ab = g_ab[t[b]];
    float sa = sqrtf(ab), sb = sqrtf(1.0f - ab);

    for (int i = tid; i < DM; i += 256){ gt[i] = g_gctx[b*DM + i]; gt[DM + i] = g_temb[b*DM + i]; }
    {
        const float* fb = fut + (size_t)b*TFD*DF;
        const float* eb = eps + (size_t)b*TFD*DF;
        for (int i = tid; i < TFD*DF; i += 256) nz[i] = sa*fb[i] + sb*eb[i];
    }
    __syncthreads();

    const float* W1e = W1 + (size_t)e*1088*512;
    const float* W2e = W2 + (size_t)e*512*64;

    // base[h] = b1 + gctx @ W1[64:576] + temb @ W1[576:1088]
    {
        int h0 = 2*tid;
        float a0 = b1[e*512 + h0], a1 = b1[e*512 + h0 + 1];
        #pragma unroll 8
        for (int k = 0; k < 1024; k++){
            float g = gt[k];
            float2 w = *(const float2*)&W1e[(size_t)(64 + k)*512 + h0];
            a0 = fmaf(g, w.x, a0);
            a1 = fmaf(g, w.y, a1);
        }
        base[h0] = a0; base[h0+1] = a1;
    }
    __syncthreads();

    float lsum = 0.0f;
    int lf0 = 2*(tid >> 4);
    int f0  = 4*(tid & 15);

    for (int th = 0; th < 2; th++){
        // phase1
        for (int hc = 0; hc < 2; hc++){
            int h = tid + hc*256;
            float wa[64];
            #pragma unroll
            for (int k = 0; k < 64; k++) wa[k] = W1e[k*512 + h];
            float bh = base[h];
            #pragma unroll 2
            for (int tf = 0; tf < 32; tf++){
                const float* x = &nz[(th*32 + tf)*64];
                float acc = bh;
                #pragma unroll
                for (int k = 0; k < 64; k += 4){
                    float4 v = *(const float4*)&x[k];
                    acc = fmaf(v.x, wa[k  ], acc);
                    acc = fmaf(v.y, wa[k+1], acc);
                    acc = fmaf(v.z, wa[k+2], acc);
                    acc = fmaf(v.w, wa[k+3], acc);
                }
                hs[tf*516 + h] = gelu_fast(acc);
            }
        }
        __syncthreads();

        // phase2
        float acc[2][4];
        #pragma unroll
        for (int i2 = 0; i2 < 2; i2++)
            #pragma unroll
            for (int jj = 0; jj < 4; jj++) acc[i2][jj] = 0.0f;

        for (int ch = 0; ch < 8; ch++){
            for (int i = tid; i < 4096; i += 256) w2c[i] = W2e[ch*4096 + i];
            __syncthreads();
            #pragma unroll 4
            for (int hh = 0; hh < 64; hh++){
                float a0 = hs[ lf0     *516 + ch*64 + hh];
                float a1 = hs[(lf0 + 1)*516 + ch*64 + hh];
                float4 w = *(const float4*)&w2c[hh*64 + f0];
                acc[0][0] = fmaf(a0, w.x, acc[0][0]);
                acc[0][1] = fmaf(a0, w.y, acc[0][1]);
                acc[0][2] = fmaf(a0, w.z, acc[0][2]);
                acc[0][3] = fmaf(a0, w.w, acc[0][3]);
                acc[1][0] = fmaf(a1, w.x, acc[1][0]);
                acc[1][1] = fmaf(a1, w.y, acc[1][1]);
                acc[1][2] = fmaf(a1, w.z, acc[1][2]);
                acc[1][3] = fmaf(a1, w.w, acc[1][3]);
            }
            __syncthreads();
        }

        #pragma unroll
        for (int i2 = 0; i2 < 2; i2++){
            int tfg = th*32 + lf0 + i2;
            #pragma unroll
            for (int jj = 0; jj < 4; jj++){
                float o = acc[i2][jj] + b2[e*64 + f0 + jj];
                if (do_store) g_outsub[(((e*4 + b)*TFD) + tfg)*DF + f0 + jj] = o;
                if (do_loss){
                    float d = o - eps[(size_t)b*4096 + tfg*64 + f0 + jj];
                    lsum += d*d;
                }
            }
        }
        __syncthreads();
    }

    if (do_loss){
        #pragma unroll
        for (int off = 16; off; off >>= 1) lsum += __shfl_xor_sync(0xffffffff, lsum, off);
        if ((tid & 31) == 0) red[tid >> 5] = lsum;
        __syncthreads();
        if (tid == 0){
            float tot = 0.0f;
            #pragma unroll
            for (int w = 0; w < 8; w++) tot += red[w];
            g_loss[b] = tot * (1.0f/4096.0f);
        }
    }
}

// ---------------- K5: final scalar ----------------
__global__ void k_final(float* __restrict__ out){
    __shared__ float s_lossw, s_chain, s_smooth;
    __shared__ float s_psum[6];
    __shared__ int   s_cnt[6];
    int tid = threadIdx.x;
    if (tid == 0){ s_lossw = 0.0f; s_chain = 0.0f; s_smooth = 0.0f; }
    if (tid < 6){ s_psum[tid] = 0.0f; s_cnt[tid] = 0; }
    __syncthreads();

    const float PW[3] = {1.0f, 5.0f, 5.0f};
    float lw = 0.0f, lp[6] = {0,0,0,0,0,0};
    int   lc[6] = {0,0,0,0,0,0};
    for (int b = tid; b < B; b += 256){
        int s = g_sel[b];
        lw += g_loss[b] * PW[s % 3];
        lc[s]++;
        #pragma unroll
        for (int e = 0; e < 6; e++) lp[e] += g_probs[b*NE + e];
    }
    atomicAdd(&s_lossw, lw);
    #pragma unroll
    for (int e = 0; e < 6; e++){ atomicAdd(&s_psum[e], lp[e]); atomicAdd(&s_cnt[e], lc[e]); }

    const int pa[7] = {0,1,3,4,0,1,2};
    const int pb[7] = {1,2,4,5,3,4,5};
    float ch = 0.0f;
    for (int i = tid; i < 16384; i += 256){
        #pragma unroll
        for (int q = 0; q < 7; q++){
            float d = g_outsub[pa[q]*16384 + i] - g_outsub[pb[q]*16384 + i];
            ch += d*d;
        }
    }
    atomicAdd(&s_chain, ch);

    float smv = 0.0f;
    for (int i = tid; i < 96768; i += 256){
        int e  = i / 16128; int r  = i - e*16128;
        int s  = r / 4032;  int r2 = r - s*4032;
        int idx = (e*4 + s)*4096 + r2;
        float d = g_outsub[idx + 64] - g_outsub[idx];
        smv += d*d;
    }
    atomicAdd(&s_smooth, smv);
    __syncthreads();

    if (tid == 0){
        float lb = 0.0f;
        #pragma unroll
        for (int e = 0; e < 6; e++)
            lb += ((float)s_cnt[e] / 512.0f) * (s_psum[e] / 512.0f);
        float total = s_lossw / 512.0f
                    + 0.01f * (s_chain / 16384.0f + 0.5f * s_smooth / 16128.0f)
                    + 0.06f * lb;
        out[0] = total;
    }
}

// ---------------- launch ----------------
extern "C" void kernel_launch(void* const* d_in, const int* in_sizes, int n_in,
                              void* d_out, int out_size){
    const float* obs  = (const float*)d_in[0];
    const float* fut  = (const float*)d_in[1];
    const float* sc   = (const float*)d_in[2];
    const float* eps  = (const float*)d_in[3];
    const int*   phase= (const int*)  d_in[4];
    const int*   t    = (const int*)  d_in[5];
    const float* Wenc = (const float*)d_in[6];
    const float* benc = (const float*)d_in[7];
    const float* Wstat= (const float*)d_in[8];
    const float* Wr   = (const float*)d_in[9];
    const float* br   = (const float*)d_in[10];
    const float* W1   = (const float*)d_in[11];
    const float* b1   = (const float*)d_in[12];
    const float* W2   = (const float*)d_in[13];
    const float* b2   = (const float*)d_in[14];

    const int SMEM_CTX    = (256*APAD + 128*APAD)*2 + 2*128*4;      // 56,320 B
    const int SMEM_EXPERT = (1024 + 512 + 4096 + 32*516 + 4096)*4;  // 104,960 B
    static bool attr_done = false;
    if (!attr_done){
        cudaFuncSetAttribute(k_ctx_mma, cudaFuncAttributeMaxDynamicSharedMemorySize, SMEM_CTX);
        cudaFuncSetAttribute(k_expert,  cudaFuncAttributeMaxDynamicSharedMemorySize, SMEM_EXPERT);
        attr_done = true;
    }

    k_init   <<<1, 32>>>();
    k_temb   <<<B, 256>>>(t);
    k_ctx_mma<<<dim3(4, B), 512, SMEM_CTX>>>(obs, sc, Wenc, benc, Wstat);
    k_router <<<64, 256>>>(Wr, br, phase);
    k_expert <<<NPAIR, 256, SMEM_EXPERT>>>(fut, eps, t, W1, b1, W2, b2);
    k_final  <<<1, 256>>>((float*)d_out);
}

// round 5
// speedup vs baseline: 2.2360x; 1.3513x over previous
#include <cuda_runtime.h>
#include <cuda_bf16.h>
#include <math.h>

#define B   512
#define TP  256
#define DM  512
#define DS  32
#define NE  6
#define NPAIR 532

// ---------------- device scratch ----------------
__device__ float g_ab[1000];
__device__ float g_gctx[B*DM];
__device__ float g_temb[B*DM];
__device__ float g_probs[B*NE];
__device__ int   g_sel[B];
__device__ float g_loss[B];
__device__ float g_outsub[NE*4*64*64];
__device__ int   g_cnt[NE];
__device__ int   g_list[NE*512];
__device__ float g_base[NE*B*512];
__device__ __nv_bfloat16 c_W1n[NE*512*64];
__device__ __nv_bfloat16 c_W1b[(size_t)NE*512*1024];
__device__ __nv_bfloat16 c_W2t[NE*64*512];

__device__ __forceinline__ float gelu_fast(float x){
    float s = x*x;
    float p = x * fmaf(s, 0.044715f, 1.0f);
    float argv = p * -2.3022083f;          // -2*0.79788456*log2(e)
    float e;
    asm("ex2.approx.f32 %0, %1;" : "=f"(e) : "f"(argv));
    float r;
    asm("rcp.approx.f32 %0, %1;" : "=f"(r) : "f"(e + 1.0f));
    return x * r;
}

__device__ __forceinline__ void mma16816(float* c, const unsigned* a, unsigned b0, unsigned b1){
    asm("mma.sync.aligned.m16n8k16.row.col.f32.bf16.bf16.f32 "
        "{%0,%1,%2,%3}, {%4,%5,%6,%7}, {%8,%9}, {%0,%1,%2,%3};"
        : "+f"(c[0]), "+f"(c[1]), "+f"(c[2]), "+f"(c[3])
        : "r"(a[0]), "r"(a[1]), "r"(a[2]), "r"(a[3]), "r"(b0), "r"(b1));
}

// ---------------- K0 ----------------
__global__ void k_init(){
    if (threadIdx.x < NE) g_cnt[threadIdx.x] = 0;
    if (threadIdx.x == 0){
        float ab = 1.0f;
        const float step = (0.02f - 0.0001f) / 999.0f;
        for (int i = 0; i < 1000; i++){
            float beta = 0.0001f + step * (float)i;
            ab *= (1.0f - beta);
            g_ab[i] = ab;
        }
    }
}

// ---------------- K1 ----------------
__global__ void k_temb(const int* __restrict__ t){
    int b = blockIdx.x;
    float tv = (float)t[b];
    for (int j = threadIdx.x; j < DM; j += blockDim.x){
        int i = (j < 256) ? j : (j - 256);
        float freq = expf(-9.210340371976184f * (float)i / 256.0f);
        float a = tv * freq;
        g_temb[b*DM + j] = (j < 256) ? sinf(a) : cosf(a);
    }
}

// ---------------- converts: W1 -> W1n^T / W1b^T, W2 -> W2t ----------------
__global__ void k_convert_w1(const float* __restrict__ W1){
    __shared__ float sm[32][33];
    int e = blockIdx.z, kt = blockIdx.y, ht = blockIdx.x;
    int tid = threadIdx.x;
    int i = tid >> 3, j4 = (tid & 7) * 4;
    float4 v = *(const float4*)&W1[((size_t)e*1088 + kt*32 + i)*512 + ht*32 + j4];
    sm[i][j4] = v.x; sm[i][j4+1] = v.y; sm[i][j4+2] = v.z; sm[i][j4+3] = v.w;
    __syncthreads();
    int h = ht*32 + i;
    int k = kt*32 + j4;
    __nv_bfloat162 p0 = __floats2bfloat162_rn(sm[j4][i],   sm[j4+1][i]);
    __nv_bfloat162 p1 = __floats2bfloat162_rn(sm[j4+2][i], sm[j4+3][i]);
    __nv_bfloat16* dst;
    if (kt < 2) dst = c_W1n + ((size_t)e*512 + h)*64 + k;
    else        dst = c_W1b + ((size_t)e*512 + h)*1024 + (k - 64);
    *(__nv_bfloat162*)dst       = p0;
    *(__nv_bfloat162*)(dst + 2) = p1;
}

__global__ void k_convert_w2(const float* __restrict__ W2){
    __shared__ float sm[32][33];
    int e = blockIdx.z, ht = blockIdx.y, ft = blockIdx.x;
    int tid = threadIdx.x;
    int i = tid >> 3, j4 = (tid & 7) * 4;
    float4 v = *(const float4*)&W2[((size_t)e*512 + ht*32 + i)*64 + ft*32 + j4];
    sm[i][j4] = v.x; sm[i][j4+1] = v.y; sm[i][j4+2] = v.z; sm[i][j4+3] = v.w;
    __syncthreads();
    int f = ft*32 + i;
    int h = ht*32 + j4;
    __nv_bfloat162 p0 = __floats2bfloat162_rn(sm[j4][i],   sm[j4+1][i]);
    __nv_bfloat162 p1 = __floats2bfloat162_rn(sm[j4+2][i], sm[j4+3][i]);
    __nv_bfloat16* dst = c_W2t + ((size_t)e*64 + f)*512 + h;
    *(__nv_bfloat162*)dst       = p0;
    *(__nv_bfloat162*)(dst + 2) = p1;
}

// ---------------- K2: ctx GEMM (validated R4) ----------------
#define APAD 72
__global__ void __launch_bounds__(512, 1)
k_ctx_mma(const float* __restrict__ obs, const float* __restrict__ sc,
          const float* __restrict__ Wenc, const float* __restrict__ benc,
          const float* __restrict__ Wstat){
    extern __shared__ char smraw[];
    __nv_bfloat16* As = (__nv_bfloat16*)smraw;
    __nv_bfloat16* Bs = As + 256*APAD;
    float* pre    = (float*)(Bs + 128*APAD);
    float* colsum = pre + 128;

    int b  = blockIdx.y;
    int n0 = blockIdx.x * 128;
    int tid = threadIdx.x;

    {
        int row = tid >> 1;
        int c0  = (tid & 1) * 32;
        const float4* src = (const float4*)(obs + (size_t)b*TP*64 + row*64 + c0);
        __nv_bfloat16* arow = As + row*APAD + c0;
        #pragma unroll
        for (int i = 0; i < 8; i++){
            float4 v = src[i];
            *(__nv_bfloat162*)(arow + i*4    ) = __floats2bfloat162_rn(v.x, v.y);
            *(__nv_bfloat162*)(arow + i*4 + 2) = __floats2bfloat162_rn(v.z, v.w);
        }
    }
    {
        int j  = tid >> 2;
        int kq = (tid & 3) * 16;
        int jg = n0 + j;
        #pragma unroll
        for (int i = 0; i < 16; i++)
            Bs[j*APAD + kq + i] = __float2bfloat16_rn(Wenc[(kq + i)*DM + jg]);
    }
    if (tid < 128){
        int jg = n0 + tid;
        float acc = benc[jg];
        #pragma unroll
        for (int k = 0; k < 32; k++) acc = fmaf(sc[b*DS + k], Wstat[k*DM + jg], acc);
        pre[tid] = acc;
        colsum[tid] = 0.0f;
    }
    __syncthreads();

    int warp = tid >> 5, lane = tid & 31;
    int m0 = (warp >> 1) * 32;
    int nb = (warp & 1) * 64;
    int qrow = lane >> 2;
    int qk2  = (lane & 3) * 2;

    float c[2][8][4];
    #pragma unroll
    for (int mt = 0; mt < 2; mt++)
        #pragma unroll
        for (int nt = 0; nt < 8; nt++)
            #pragma unroll
            for (int r = 0; r < 4; r++) c[mt][nt][r] = 0.0f;

    #pragma unroll
    for (int kk = 0; kk < 4; kk++){
        unsigned a[2][4];
        #pragma unroll
        for (int mt = 0; mt < 2; mt++){
            const __nv_bfloat16* ap = As + (m0 + mt*16 + qrow)*APAD + kk*16 + qk2;
            a[mt][0] = *(const unsigned*)(ap);
            a[mt][1] = *(const unsigned*)(ap + 8*APAD);
            a[mt][2] = *(const unsigned*)(ap + 8);
            a[mt][3] = *(const unsigned*)(ap + 8*APAD + 8);
        }
        #pragma unroll
        for (int nt = 0; nt < 8; nt++){
            const __nv_bfloat16* bp = Bs + (nb + nt*8 + qrow)*APAD + kk*16 + qk2;
            unsigned b0 = *(const unsigned*)(bp);
            unsigned b1 = *(const unsigned*)(bp + 8);
            mma16816(c[0][nt], a[0], b0, b1);
            mma16816(c[1][nt], a[1], b0, b1);
        }
    }

    #pragma unroll
    for (int nt = 0; nt < 8; nt++){
        int jl = nb + nt*8 + qk2;
        float p0 = pre[jl], p1 = pre[jl + 1];
        float s0 = 0.0f, s1 = 0.0f;
        #pragma unroll
        for (int mt = 0; mt < 2; mt++){
            s0 += gelu_fast(c[mt][nt][0] + p0) + gelu_fast(c[mt][nt][2] + p0);
            s1 += gelu_fast(c[mt][nt][1] + p1) + gelu_fast(c[mt][nt][3] + p1);
        }
        #pragma unroll
        for (int off = 16; off >= 4; off >>= 1){
            s0 += __shfl_xor_sync(0xffffffff, s0, off);
            s1 += __shfl_xor_sync(0xffffffff, s1, off);
        }
        if (qrow == 0){
            atomicAdd(&colsum[jl    ], s0);
            atomicAdd(&colsum[jl + 1], s1);
        }
    }
    __syncthreads();

    if (tid < 128)
        g_gctx[b*DM + n0 + tid] = colsum[tid] * (1.0f/256.0f);
}

// ---------------- K3: router + softmax + selection + expert lists ----------------
__global__ void k_router(const float* __restrict__ Wr, const float* __restrict__ br,
                         const int* __restrict__ phase){
    int warp = threadIdx.x >> 5;
    int lane = threadIdx.x & 31;
    int b = blockIdx.x*8 + warp;
    float p[6] = {0,0,0,0,0,0};
    for (int k = lane; k < DM; k += 32){
        float g = g_gctx[b*DM + k];
        const float* w = Wr + k*NE;
        #pragma unroll
        for (int e = 0; e < 6; e++) p[e] = fmaf(g, w[e], p[e]);
    }
    #pragma unroll
    for (int off = 16; off; off >>= 1){
        #pragma unroll
        for (int e = 0; e < 6; e++) p[e] += __shfl_xor_sync(0xffffffff, p[e], off);
    }
    if (lane == 0){
        float l[6], pr[6];
        #pragma unroll
        for (int e = 0; e < 6; e++) l[e] = p[e] + br[e];
        float m = l[0];
        #pragma unroll
        for (int e = 1; e < 6; e++) m = fmaxf(m, l[e]);
        float s = 0.0f;
        #pragma unroll
        for (int e = 0; e < 6; e++){ pr[e] = expf(l[e] - m); s += pr[e]; }
        float inv = 1.0f / s;
        #pragma unroll
        for (int e = 0; e < 6; e++){ pr[e] *= inv; g_probs[b*NE + e] = pr[e]; }
        int pl = phase[b];
        int sel = pl + ((pr[pl+3] > pr[pl]) ? 3 : 0);
        g_sel[b] = sel;
        if (b < 4){
            #pragma unroll
            for (int e = 0; e < 6; e++){
                int idx = atomicAdd(&g_cnt[e], 1);
                g_list[e*512 + idx] = b;
            }
        } else {
            int idx = atomicAdd(&g_cnt[sel], 1);
            g_list[sel*512 + idx] = b;
        }
    }
}

// ---------------- K3c: base[e][b][h] via bf16 MMA ----------------
// grid (6, 16); 256 thr; M=32 samples, N=512 h, K=1024
__global__ void __launch_bounds__(256, 1)
k_base(const float* __restrict__ b1){
    extern __shared__ char smraw[];
    __nv_bfloat16* As = (__nv_bfloat16*)smraw;   // 32 x 1032
    __nv_bfloat16* Bs = As + 32*1032;            // 512 x 72
    int* bl = (int*)(Bs + 512*72);               // 32

    int e = blockIdx.x, tile = blockIdx.y;
    int n = g_cnt[e], s0 = tile*32;
    if (s0 >= n) return;
    int tid = threadIdx.x;

    if (tid < 32){
        int s = s0 + tid;
        bl[tid] = (s < n) ? g_list[e*512 + s] : g_list[e*512];
    }
    __syncthreads();

    {
        int r = tid >> 3, seg = tid & 7;
        int bb = bl[r];
        const float4* src = (const float4*)((seg < 4)
            ? (g_gctx + bb*512 + seg*128)
            : (g_temb + bb*512 + seg*128 - 512));
        __nv_bfloat16* dst = As + r*1032 + seg*128;
        #pragma unroll
        for (int i = 0; i < 32; i++){
            float4 v = src[i];
            *(__nv_bfloat162*)(dst + i*4    ) = __floats2bfloat162_rn(v.x, v.y);
            *(__nv_bfloat162*)(dst + i*4 + 2) = __floats2bfloat162_rn(v.z, v.w);
        }
    }

    int warp = tid >> 5, lane = tid & 31;
    int qrow = lane >> 5 ? 0 : (lane >> 2);   // lane>>2
    qrow = lane >> 2;
    int qk2 = (lane & 3) * 2;
    int nb = warp * 64;

    float acc[2][8][4];
    #pragma unroll
    for (int mt = 0; mt < 2; mt++)
        #pragma unroll
        for (int nt = 0; nt < 8; nt++)
            #pragma unroll
            for (int r = 0; r < 4; r++) acc[mt][nt][r] = 0.0f;

    for (int kc = 0; kc < 16; kc++){
        __syncthreads();
        #pragma unroll
        for (int i = 0; i < 2; i++){
            int h = tid + i*256;
            const int4* s4 = (const int4*)(c_W1b + ((size_t)e*512 + h)*1024 + kc*64);
            int4* d4 = (int4*)(Bs + h*72);
            #pragma unroll
            for (int q = 0; q < 8; q++) d4[q] = s4[q];
        }
        __syncthreads();

        unsigned a[2][4][4];
        #pragma unroll
        for (int mt = 0; mt < 2; mt++)
            #pragma unroll
            for (int ks = 0; ks < 4; ks++){
                const __nv_bfloat16* ap = As + (mt*16 + qrow)*1032 + kc*64 + ks*16 + qk2;
                a[mt][ks][0] = *(const unsigned*)(ap);
                a[mt][ks][1] = *(const unsigned*)(ap + 8*1032);
                a[mt][ks][2] = *(const unsigned*)(ap + 8);
                a[mt][ks][3] = *(const unsigned*)(ap + 8*1032 + 8);
            }
        #pragma unroll
        for (int nt = 0; nt < 8; nt++){
            #pragma unroll
            for (int ks = 0; ks < 4; ks++){
                const __nv_bfloat16* bp = Bs + (nb + nt*8 + qrow)*72 + ks*16 + qk2;
                unsigned b0 = *(const unsigned*)(bp);
                unsigned b1v = *(const unsigned*)(bp + 8);
                mma16816(acc[0][nt], a[0][ks], b0, b1v);
                mma16816(acc[1][nt], a[1][ks], b0, b1v);
            }
        }
    }

    #pragma unroll
    for (int mt = 0; mt < 2; mt++){
        #pragma unroll
        for (int half = 0; half < 2; half++){
            int r = mt*16 + qrow + half*8;
            if (s0 + r < n){
                int bb = bl[r];
                float* dst = g_base + ((size_t)e*B + bb)*512;
                #pragma unroll
                for (int nt = 0; nt < 8; nt++){
                    int h = nb + nt*8 + qk2;
                    float2 o;
                    o.x = acc[mt][nt][half*2    ] + b1[e*512 + h];
                    o.y = acc[mt][nt][half*2 + 1] + b1[e*512 + h + 1];
                    *(float2*)(dst + h) = o;
                }
            }
        }
    }
}

// ---------------- K4: expert MLP via bf16 MMA ----------------
__global__ void __launch_bounds__(256, 1)
k_expert(const float* __restrict__ fut, const float* __restrict__ eps,
         const int* __restrict__ t, const float* __restrict__ b2){
    extern __shared__ char smraw[];
    __nv_bfloat16* nzs = (__nv_bfloat16*)smraw;       // 64 x 72
    __nv_bfloat16* w1s = nzs + 64*72;                 // 512 x 72 (reused as w2s 64x520)
    __nv_bfloat16* hss = w1s + 512*72;                // 64 x 520
    float* basev = (float*)(hss + 64*520);            // 512
    __shared__ float red[8];

    int p = blockIdx.x;
    int b, e;
    if (p < 24){ b = p / 6; e = p - b*6; }
    else       { b = p - 20; e = g_sel[p - 20]; }
    int tid = threadIdx.x;
    bool do_loss  = (e == g_sel[b]);
    bool do_store = (b < 4);

    float ab = g_ab[t[b]];
    float sa = sqrtf(ab), sb = sqrtf(1.0f - ab);

    {   // nzs = bf16(noisy)
        int r = tid >> 2, c0 = (tid & 3) * 16;
        const float4* f4 = (const float4*)(fut + (size_t)b*4096 + r*64 + c0);
        const float4* e4 = (const float4*)(eps + (size_t)b*4096 + r*64 + c0);
        __nv_bfloat16* dst = nzs + r*72 + c0;
        #pragma unroll
        for (int i = 0; i < 4; i++){
            float4 vf = f4[i], ve = e4[i];
            *(__nv_bfloat162*)(dst + i*4    ) = __floats2bfloat162_rn(fmaf(sa,vf.x,sb*ve.x), fmaf(sa,vf.y,sb*ve.y));
            *(__nv_bfloat162*)(dst + i*4 + 2) = __floats2bfloat162_rn(fmaf(sa,vf.z,sb*ve.z), fmaf(sa,vf.w,sb*ve.w));
        }
    }
    #pragma unroll
    for (int i = 0; i < 2; i++){   // w1s
        int h = tid + i*256;
        const int4* s4 = (const int4*)(c_W1n + ((size_t)e*512 + h)*64);
        int4* d4 = (int4*)(w1s + h*72);
        #pragma unroll
        for (int q = 0; q < 8; q++) d4[q] = s4[q];
    }
    basev[tid]       = g_base[((size_t)e*B + b)*512 + tid];
    basev[tid + 256] = g_base[((size_t)e*B + b)*512 + tid + 256];
    __syncthreads();

    int warp = tid >> 5, lane = tid & 31;
    int qrow = lane >> 2, qk2 = (lane & 3) * 2;
    int m0 = (warp >> 2) * 32;        // 2 m-warps
    int n0 = (warp & 3) * 128;        // 4 n-warps (phase1)

    // ---- phase1: hs = gelu(nz @ W1n^T + base), M=64 N=512 K=64 ----
    {
        unsigned a[2][4][4];
        #pragma unroll
        for (int mt = 0; mt < 2; mt++)
            #pragma unroll
            for (int ks = 0; ks < 4; ks++){
                const __nv_bfloat16* ap = nzs + (m0 + mt*16 + qrow)*72 + ks*16 + qk2;
                a[mt][ks][0] = *(const unsigned*)(ap);
                a[mt][ks][1] = *(const unsigned*)(ap + 8*72);
                a[mt][ks][2] = *(const unsigned*)(ap + 8);
                a[mt][ks][3] = *(const unsigned*)(ap + 8*72 + 8);
            }
        #pragma unroll 4
        for (int nto = 0; nto < 16; nto++){
            int h8 = n0 + nto*8;
            float c0v[2][4];
            #pragma unroll
            for (int mt = 0; mt < 2; mt++)
                #pragma unroll
                for (int r = 0; r < 4; r++) c0v[mt][r] = 0.0f;
            #pragma unroll
            for (int ks = 0; ks < 4; ks++){
                const __nv_bfloat16* bp = w1s + (h8 + qrow)*72 + ks*16 + qk2;
                unsigned b0 = *(const unsigned*)(bp);
                unsigned b1v = *(const unsigned*)(bp + 8);
                mma16816(c0v[0], a[0][ks], b0, b1v);
                mma16816(c0v[1], a[1][ks], b0, b1v);
            }
            int h = h8 + qk2;
            float ba0 = basev[h], ba1 = basev[h+1];
            #pragma unroll
            for (int mt = 0; mt < 2; mt++){
                int r = m0 + mt*16 + qrow;
                *(__nv_bfloat162*)(hss + r*520 + h) =
                    __floats2bfloat162_rn(gelu_fast(c0v[mt][0] + ba0), gelu_fast(c0v[mt][1] + ba1));
                *(__nv_bfloat162*)(hss + (r+8)*520 + h) =
                    __floats2bfloat162_rn(gelu_fast(c0v[mt][2] + ba0), gelu_fast(c0v[mt][3] + ba1));
            }
        }
    }
    __syncthreads();

    // ---- stage W2t into w1s region ----
    __nv_bfloat16* w2s = w1s;   // [64][520]
    {
        int f = tid >> 2, seg = tid & 3;
        const int4* s4 = (const int4*)(c_W2t + ((size_t)e*64 + f)*512) + seg*16;
        int4* d4 = (int4*)(w2s + f*520) + seg*16;
        #pragma unroll
        for (int q = 0; q < 16; q++) d4[q] = s4[q];
    }
    __syncthreads();

    // ---- phase2: out = hs @ W2t^T, M=64 N=64 K=512 ----
    int f0 = (warp & 3) * 16;
    float acc[2][2][4];
    #pragma unroll
    for (int mt = 0; mt < 2; mt++)
        #pragma unroll
        for (int nt = 0; nt < 2; nt++)
            #pragma unroll
            for (int r = 0; r < 4; r++) acc[mt][nt][r] = 0.0f;

    #pragma unroll 4
    for (int ks = 0; ks < 32; ks++){
        unsigned a[2][4];
        #pragma unroll
        for (int mt = 0; mt < 2; mt++){
            const __nv_bfloat16* ap = hss + (m0 + mt*16 + qrow)*520 + ks*16 + qk2;
            a[mt][0] = *(const unsigned*)(ap);
            a[mt][1] = *(const unsigned*)(ap + 8*520);
            a[mt][2] = *(const unsigned*)(ap + 8);
            a[mt][3] = *(const unsigned*)(ap + 8*520 + 8);
        }
        #pragma unroll
        for (int nt = 0; nt < 2; nt++){
            const __nv_bfloat16* bp = w2s + (f0 + nt*8 + qrow)*520 + ks*16 + qk2;
            unsigned b0 = *(const unsigned*)(bp);
            unsigned b1v = *(const unsigned*)(bp + 8);
            mma16816(acc[0][nt], a[0], b0, b1v);
            mma16816(acc[1][nt], a[1], b0, b1v);
        }
    }

    float lsum = 0.0f;
    #pragma unroll
    for (int mt = 0; mt < 2; mt++){
        #pragma unroll
        for (int nt = 0; nt < 2; nt++){
            int fcol = f0 + nt*8 + qk2;
            float bb0 = b2[e*64 + fcol], bb1 = b2[e*64 + fcol + 1];
            #pragma unroll
            for (int half = 0; half < 2; half++){
                int r = m0 + mt*16 + qrow + half*8;
                float o0 = acc[mt][nt][half*2    ] + bb0;
                float o1 = acc[mt][nt][half*2 + 1] + bb1;
                if (do_store){
                    float2 st; st.x = o0; st.y = o1;
                    *(float2*)&g_outsub[((e*4 + b)*64 + r)*64 + fcol] = st;
                }
                if (do_loss){
                    float2 ev = *(const float2*)&eps[(size_t)b*4096 + r*64 + fcol];
                    float d0 = o0 - ev.x, d1 = o1 - ev.y;
                    lsum += d0*d0 + d1*d1;
                }
            }
        }
    }

    if (do_loss){
        #pragma unroll
        for (int off = 16; off; off >>= 1) lsum += __shfl_xor_sync(0xffffffff, lsum, off);
        if (lane == 0) red[warp] = lsum;
        __syncthreads();
        if (tid == 0){
            float tot = 0.0f;
            #pragma unroll
            for (int w = 0; w < 8; w++) tot += red[w];
            g_loss[b] = tot * (1.0f/4096.0f);
        }
    }
}

// ---------------- K5: final scalar ----------------
__global__ void k_final(float* __restrict__ out){
    __shared__ float s_lossw, s_chain, s_smooth;
    __shared__ float s_psum[6];
    __shared__ int   s_cnt[6];
    int tid = threadIdx.x;
    if (tid == 0){ s_lossw = 0.0f; s_chain = 0.0f; s_smooth = 0.0f; }
    if (tid < 6){ s_psum[tid] = 0.0f; s_cnt[tid] = 0; }
    __syncthreads();

    const float PW[3] = {1.0f, 5.0f, 5.0f};
    float lw = 0.0f, lp[6] = {0,0,0,0,0,0};
    int   lc[6] = {0,0,0,0,0,0};
    for (int b = tid; b < B; b += 256){
        int s = g_sel[b];
        lw += g_loss[b] * PW[s % 3];
        lc[s]++;
        #pragma unroll
        for (int e = 0; e < 6; e++) lp[e] += g_probs[b*NE + e];
    }
    atomicAdd(&s_lossw, lw);
    #pragma unroll
    for (int e = 0; e < 6; e++){ atomicAdd(&s_psum[e], lp[e]); atomicAdd(&s_cnt[e], lc[e]); }

    const int pa[7] = {0,1,3,4,0,1,2};
    const int pb[7] = {1,2,4,5,3,4,5};
    float ch = 0.0f;
    for (int i = tid; i < 16384; i += 256){
        #pragma unroll
        for (int q = 0; q < 7; q++){
            float d = g_outsub[pa[q]*16384 + i] - g_outsub[pb[q]*16384 + i];
            ch += d*d;
        }
    }
    atomicAdd(&s_chain, ch);

    float smv = 0.0f;
    for (int i = tid; i < 96768; i += 256){
        int e  = i / 16128; int r  = i - e*16128;
        int s  = r / 4032;  int r2 = r - s*4032;
        int idx = (e*4 + s)*4096 + r2;
        float d = g_outsub[idx + 64] - g_outsub[idx];
        smv += d*d;
    }
    atomicAdd(&s_smooth, smv);
    __syncthreads();

    if (tid == 0){
        float lb = 0.0f;
        #pragma unroll
        for (int e = 0; e < 6; e++)
            lb += ((float)s_cnt[e] / 512.0f) * (s_psum[e] / 512.0f);
        float total = s_lossw / 512.0f
                    + 0.01f * (s_chain / 16384.0f + 0.5f * s_smooth / 16128.0f)
                    + 0.06f * lb;
        out[0] = total;
    }
}

// ---------------- launch ----------------
extern "C" void kernel_launch(void* const* d_in, const int* in_sizes, int n_in,
                              void* d_out, int out_size){
    const float* obs  = (const float*)d_in[0];
    const float* fut  = (const float*)d_in[1];
    const float* sc   = (const float*)d_in[2];
    const float* eps  = (const float*)d_in[3];
    const int*   phase= (const int*)  d_in[4];
    const int*   t    = (const int*)  d_in[5];
    const float* Wenc = (const float*)d_in[6];
    const float* benc = (const float*)d_in[7];
    const float* Wstat= (const float*)d_in[8];
    const float* Wr   = (const float*)d_in[9];
    const float* br   = (const float*)d_in[10];
    const float* W1   = (const float*)d_in[11];
    const float* b1   = (const float*)d_in[12];
    const float* W2   = (const float*)d_in[13];
    const float* b2   = (const float*)d_in[14];

    const int SMEM_CTX  = (256*APAD + 128*APAD)*2 + 2*128*4;                 // 56,320
    const int SMEM_BASE = (32*1032 + 512*72)*2 + 32*4;                       // 139,904
    const int SMEM_EXP  = (64*72 + 512*72 + 64*520)*2 + 512*4 ;              // 151,552
    static bool attr_done = false;
    if (!attr_done){
        cudaFuncSetAttribute(k_ctx_mma, cudaFuncAttributeMaxDynamicSharedMemorySize, SMEM_CTX);
        cudaFuncSetAttribute(k_base,    cudaFuncAttributeMaxDynamicSharedMemorySize, SMEM_BASE);
        cudaFuncSetAttribute(k_expert,  cudaFuncAttributeMaxDynamicSharedMemorySize, SMEM_EXP);
        attr_done = true;
    }

    k_init      <<<1, 32>>>();
    k_temb      <<<B, 256>>>(t);
    k_convert_w1<<<dim3(16, 34, NE), 256>>>(W1);
    k_convert_w2<<<dim3(2, 16, NE), 256>>>(W2);
    k_ctx_mma   <<<dim3(4, B), 512, SMEM_CTX>>>(obs, sc, Wenc, benc, Wstat);
    k_router    <<<64, 256>>>(Wr, br, phase);
    k_base      <<<dim3(NE, 16), 256, SMEM_BASE>>>(b1);
    k_expert    <<<NPAIR, 256, SMEM_EXP>>>(fut, eps, t, b2);
    k_final     <<<1, 256>>>((float*)d_out);
}

// round 6
// speedup vs baseline: 2.5169x; 1.1256x over previous
#include <cuda_runtime.h>
#include <cuda_bf16.h>
#include <math.h>

#define B   512
#define TP  256
#define DM  512
#define DS  32
#define NE  6
#define NPAIR 532

// ---------------- device scratch ----------------
__device__ float g_ab[1000];
__device__ float g_gctx[B*DM];
__device__ float g_temb[B*DM];
__device__ float g_probs[B*NE];
__device__ int   g_sel[B];
__device__ float g_loss[B];
__device__ float g_outsub[NE*4*64*64];
__device__ int   g_cnt[NE];
__device__ int   g_list[NE*512];
__device__ float g_base[NE*B*512];
__device__ __nv_bfloat16 c_W1n[NE*512*64];
__device__ __nv_bfloat16 c_W1b[(size_t)NE*512*1024];
__device__ __nv_bfloat16 c_W2t[NE*64*512];
// final-reduction accumulators
__device__ float g_accL, g_accC, g_accS;
__device__ float g_psumE[NE];
__device__ float g_cntF[NE];

__device__ __forceinline__ float gelu_fast(float x){
    float s = x*x;
    float p = x * fmaf(s, 0.044715f, 1.0f);
    float argv = p * -2.3022083f;          // -2*0.79788456*log2(e)
    float e;
    asm("ex2.approx.f32 %0, %1;" : "=f"(e) : "f"(argv));
    float r;
    asm("rcp.approx.f32 %0, %1;" : "=f"(r) : "f"(e + 1.0f));
    return x * r;
}

__device__ __forceinline__ void mma16816(float* c, const unsigned* a, unsigned b0, unsigned b1){
    asm("mma.sync.aligned.m16n8k16.row.col.f32.bf16.bf16.f32 "
        "{%0,%1,%2,%3}, {%4,%5,%6,%7}, {%8,%9}, {%0,%1,%2,%3};"
        : "+f"(c[0]), "+f"(c[1]), "+f"(c[2]), "+f"(c[3])
        : "r"(a[0]), "r"(a[1]), "r"(a[2]), "r"(a[3]), "r"(b0), "r"(b1));
}

// ---------------- K0: init + zero accumulators ----------------
__global__ void k_init(){
    int tid = threadIdx.x;
    if (tid < NE){ g_cnt[tid] = 0; g_psumE[tid] = 0.0f; g_cntF[tid] = 0.0f; }
    if (tid == 6){ g_accL = 0.0f; g_accC = 0.0f; g_accS = 0.0f; }
    if (tid == 0){
        float ab = 1.0f;
        const float step = (0.02f - 0.0001f) / 999.0f;
        for (int i = 0; i < 1000; i++){
            float beta = 0.0001f + step * (float)i;
            ab *= (1.0f - beta);
            g_ab[i] = ab;
        }
    }
}

// ---------------- K1 ----------------
__global__ void k_temb(const int* __restrict__ t){
    int b = blockIdx.x;
    float tv = (float)t[b];
    for (int j = threadIdx.x; j < DM; j += blockDim.x){
        int i = (j < 256) ? j : (j - 256);
        float freq = expf(-9.210340371976184f * (float)i / 256.0f);
        float a = tv * freq;
        g_temb[b*DM + j] = (j < 256) ? sinf(a) : cosf(a);
    }
}

// ---------------- converts ----------------
__global__ void k_convert_w1(const float* __restrict__ W1){
    __shared__ float sm[32][33];
    int e = blockIdx.z, kt = blockIdx.y, ht = blockIdx.x;
    int tid = threadIdx.x;
    int i = tid >> 3, j4 = (tid & 7) * 4;
    float4 v = *(const float4*)&W1[((size_t)e*1088 + kt*32 + i)*512 + ht*32 + j4];
    sm[i][j4] = v.x; sm[i][j4+1] = v.y; sm[i][j4+2] = v.z; sm[i][j4+3] = v.w;
    __syncthreads();
    int h = ht*32 + i;
    int k = kt*32 + j4;
    __nv_bfloat162 p0 = __floats2bfloat162_rn(sm[j4][i],   sm[j4+1][i]);
    __nv_bfloat162 p1 = __floats2bfloat162_rn(sm[j4+2][i], sm[j4+3][i]);
    __nv_bfloat16* dst;
    if (kt < 2) dst = c_W1n + ((size_t)e*512 + h)*64 + k;
    else        dst = c_W1b + ((size_t)e*512 + h)*1024 + (k - 64);
    *(__nv_bfloat162*)dst       = p0;
    *(__nv_bfloat162*)(dst + 2) = p1;
}

__global__ void k_convert_w2(const float* __restrict__ W2){
    __shared__ float sm[32][33];
    int e = blockIdx.z, ht = blockIdx.y, ft = blockIdx.x;
    int tid = threadIdx.x;
    int i = tid >> 3, j4 = (tid & 7) * 4;
    float4 v = *(const float4*)&W2[((size_t)e*512 + ht*32 + i)*64 + ft*32 + j4];
    sm[i][j4] = v.x; sm[i][j4+1] = v.y; sm[i][j4+2] = v.z; sm[i][j4+3] = v.w;
    __syncthreads();
    int f = ft*32 + i;
    int h = ht*32 + j4;
    __nv_bfloat162 p0 = __floats2bfloat162_rn(sm[j4][i],   sm[j4+1][i]);
    __nv_bfloat162 p1 = __floats2bfloat162_rn(sm[j4+2][i], sm[j4+3][i]);
    __nv_bfloat16* dst = c_W2t + ((size_t)e*64 + f)*512 + h;
    *(__nv_bfloat162*)dst       = p0;
    *(__nv_bfloat162*)(dst + 2) = p1;
}

// ---------------- K2: ctx GEMM (validated) ----------------
#define APAD 72
__global__ void __launch_bounds__(512, 1)
k_ctx_mma(const float* __restrict__ obs, const float* __restrict__ sc,
          const float* __restrict__ Wenc, const float* __restrict__ benc,
          const float* __restrict__ Wstat){
    extern __shared__ char smraw[];
    __nv_bfloat16* As = (__nv_bfloat16*)smraw;
    __nv_bfloat16* Bs = As + 256*APAD;
    float* pre    = (float*)(Bs + 128*APAD);
    float* colsum = pre + 128;

    int b  = blockIdx.y;
    int n0 = blockIdx.x * 128;
    int tid = threadIdx.x;

    {
        int row = tid >> 1;
        int c0  = (tid & 1) * 32;
        const float4* src = (const float4*)(obs + (size_t)b*TP*64 + row*64 + c0);
        __nv_bfloat16* arow = As + row*APAD + c0;
        #pragma unroll
        for (int i = 0; i < 8; i++){
            float4 v = src[i];
            *(__nv_bfloat162*)(arow + i*4    ) = __floats2bfloat162_rn(v.x, v.y);
            *(__nv_bfloat162*)(arow + i*4 + 2) = __floats2bfloat162_rn(v.z, v.w);
        }
    }
    {
        int j  = tid >> 2;
        int kq = (tid & 3) * 16;
        int jg = n0 + j;
        #pragma unroll
        for (int i = 0; i < 16; i++)
            Bs[j*APAD + kq + i] = __float2bfloat16_rn(Wenc[(kq + i)*DM + jg]);
    }
    if (tid < 128){
        int jg = n0 + tid;
        float acc = benc[jg];
        #pragma unroll
        for (int k = 0; k < 32; k++) acc = fmaf(sc[b*DS + k], Wstat[k*DM + jg], acc);
        pre[tid] = acc;
        colsum[tid] = 0.0f;
    }
    __syncthreads();

    int warp = tid >> 5, lane = tid & 31;
    int m0 = (warp >> 1) * 32;
    int nb = (warp & 1) * 64;
    int qrow = lane >> 2;
    int qk2  = (lane & 3) * 2;

    float c[2][8][4];
    #pragma unroll
    for (int mt = 0; mt < 2; mt++)
        #pragma unroll
        for (int nt = 0; nt < 8; nt++)
            #pragma unroll
            for (int r = 0; r < 4; r++) c[mt][nt][r] = 0.0f;

    #pragma unroll
    for (int kk = 0; kk < 4; kk++){
        unsigned a[2][4];
        #pragma unroll
        for (int mt = 0; mt < 2; mt++){
            const __nv_bfloat16* ap = As + (m0 + mt*16 + qrow)*APAD + kk*16 + qk2;
            a[mt][0] = *(const unsigned*)(ap);
            a[mt][1] = *(const unsigned*)(ap + 8*APAD);
            a[mt][2] = *(const unsigned*)(ap + 8);
            a[mt][3] = *(const unsigned*)(ap + 8*APAD + 8);
        }
        #pragma unroll
        for (int nt = 0; nt < 8; nt++){
            const __nv_bfloat16* bp = Bs + (nb + nt*8 + qrow)*APAD + kk*16 + qk2;
            unsigned b0 = *(const unsigned*)(bp);
            unsigned b1 = *(const unsigned*)(bp + 8);
            mma16816(c[0][nt], a[0], b0, b1);
            mma16816(c[1][nt], a[1], b0, b1);
        }
    }

    #pragma unroll
    for (int nt = 0; nt < 8; nt++){
        int jl = nb + nt*8 + qk2;
        float p0 = pre[jl], p1 = pre[jl + 1];
        float s0 = 0.0f, s1 = 0.0f;
        #pragma unroll
        for (int mt = 0; mt < 2; mt++){
            s0 += gelu_fast(c[mt][nt][0] + p0) + gelu_fast(c[mt][nt][2] + p0);
            s1 += gelu_fast(c[mt][nt][1] + p1) + gelu_fast(c[mt][nt][3] + p1);
        }
        #pragma unroll
        for (int off = 16; off >= 4; off >>= 1){
            s0 += __shfl_xor_sync(0xffffffff, s0, off);
            s1 += __shfl_xor_sync(0xffffffff, s1, off);
        }
        if (qrow == 0){
            atomicAdd(&colsum[jl    ], s0);
            atomicAdd(&colsum[jl + 1], s1);
        }
    }
    __syncthreads();

    if (tid < 128)
        g_gctx[b*DM + n0 + tid] = colsum[tid] * (1.0f/256.0f);
}

// ---------------- K3: router (smem Wr, float4 gctx) ----------------
__global__ void k_router(const float* __restrict__ Wr, const float* __restrict__ br,
                         const int* __restrict__ phase){
    __shared__ float wsh[DM*NE];   // 12 KB
    int tid = threadIdx.x;         // 256
    for (int i = tid; i < DM*NE/2; i += 256)
        ((float2*)wsh)[i] = ((const float2*)Wr)[i];
    __syncthreads();

    int warp = tid >> 5, lane = tid & 31;
    int b = blockIdx.x*8 + warp;
    float p[6] = {0,0,0,0,0,0};
    #pragma unroll
    for (int it = 0; it < 4; it++){
        int k0 = it*128 + lane*4;
        float4 g = *(const float4*)&g_gctx[b*DM + k0];
        #pragma unroll
        for (int j = 0; j < 4; j++){
            float gv = (&g.x)[j];
            const float* w = wsh + (k0 + j)*NE;
            #pragma unroll
            for (int e = 0; e < 6; e++) p[e] = fmaf(gv, w[e], p[e]);
        }
    }
    #pragma unroll
    for (int off = 16; off; off >>= 1){
        #pragma unroll
        for (int e = 0; e < 6; e++) p[e] += __shfl_xor_sync(0xffffffff, p[e], off);
    }
    if (lane == 0){
        float l[6], pr[6];
        #pragma unroll
        for (int e = 0; e < 6; e++) l[e] = p[e] + br[e];
        float m = l[0];
        #pragma unroll
        for (int e = 1; e < 6; e++) m = fmaxf(m, l[e]);
        float s = 0.0f;
        #pragma unroll
        for (int e = 0; e < 6; e++){ pr[e] = expf(l[e] - m); s += pr[e]; }
        float inv = 1.0f / s;
        #pragma unroll
        for (int e = 0; e < 6; e++){ pr[e] *= inv; g_probs[b*NE + e] = pr[e]; }
        int pl = phase[b];
        int sel = pl + ((pr[pl+3] > pr[pl]) ? 3 : 0);
        g_sel[b] = sel;
        if (b < 4){
            #pragma unroll
            for (int e = 0; e < 6; e++){
                int idx = atomicAdd(&g_cnt[e], 1);
                g_list[e*512 + idx] = b;
            }
        } else {
            int idx = atomicAdd(&g_cnt[sel], 1);
            g_list[sel*512 + idx] = b;
        }
    }
}

// ---------------- K3c: base via bf16 MMA (validated) ----------------
__global__ void __launch_bounds__(256, 1)
k_base(const float* __restrict__ b1){
    extern __shared__ char smraw[];
    __nv_bfloat16* As = (__nv_bfloat16*)smraw;   // 32 x 1032
    __nv_bfloat16* Bs = As + 32*1032;            // 512 x 72
    int* bl = (int*)(Bs + 512*72);               // 32

    int e = blockIdx.x, tile = blockIdx.y;
    int n = g_cnt[e], s0 = tile*32;
    if (s0 >= n) return;
    int tid = threadIdx.x;

    if (tid < 32){
        int s = s0 + tid;
        bl[tid] = (s < n) ? g_list[e*512 + s] : g_list[e*512];
    }
    __syncthreads();

    {
        int r = tid >> 3, seg = tid & 7;
        int bb = bl[r];
        const float4* src = (const float4*)((seg < 4)
            ? (g_gctx + bb*512 + seg*128)
            : (g_temb + bb*512 + seg*128 - 512));
        __nv_bfloat16* dst = As + r*1032 + seg*128;
        #pragma unroll
        for (int i = 0; i < 32; i++){
            float4 v = src[i];
            *(__nv_bfloat162*)(dst + i*4    ) = __floats2bfloat162_rn(v.x, v.y);
            *(__nv_bfloat162*)(dst + i*4 + 2) = __floats2bfloat162_rn(v.z, v.w);
        }
    }

    int warp = tid >> 5, lane = tid & 31;
    int qrow = lane >> 2;
    int qk2 = (lane & 3) * 2;
    int nb = warp * 64;

    float acc[2][8][4];
    #pragma unroll
    for (int mt = 0; mt < 2; mt++)
        #pragma unroll
        for (int nt = 0; nt < 8; nt++)
            #pragma unroll
            for (int r = 0; r < 4; r++) acc[mt][nt][r] = 0.0f;

    for (int kc = 0; kc < 16; kc++){
        __syncthreads();
        #pragma unroll
        for (int i = 0; i < 2; i++){
            int h = tid + i*256;
            const int4* s4 = (const int4*)(c_W1b + ((size_t)e*512 + h)*1024 + kc*64);
            int4* d4 = (int4*)(Bs + h*72);
            #pragma unroll
            for (int q = 0; q < 8; q++) d4[q] = s4[q];
        }
        __syncthreads();

        unsigned a[2][4][4];
        #pragma unroll
        for (int mt = 0; mt < 2; mt++)
            #pragma unroll
            for (int ks = 0; ks < 4; ks++){
                const __nv_bfloat16* ap = As + (mt*16 + qrow)*1032 + kc*64 + ks*16 + qk2;
                a[mt][ks][0] = *(const unsigned*)(ap);
                a[mt][ks][1] = *(const unsigned*)(ap + 8*1032);
                a[mt][ks][2] = *(const unsigned*)(ap + 8);
                a[mt][ks][3] = *(const unsigned*)(ap + 8*1032 + 8);
            }
        #pragma unroll
        for (int nt = 0; nt < 8; nt++){
            #pragma unroll
            for (int ks = 0; ks < 4; ks++){
                const __nv_bfloat16* bp = Bs + (nb + nt*8 + qrow)*72 + ks*16 + qk2;
                unsigned b0 = *(const unsigned*)(bp);
                unsigned b1v = *(const unsigned*)(bp + 8);
                mma16816(acc[0][nt], a[0][ks], b0, b1v);
                mma16816(acc[1][nt], a[1][ks], b0, b1v);
            }
        }
    }

    #pragma unroll
    for (int mt = 0; mt < 2; mt++){
        #pragma unroll
        for (int half = 0; half < 2; half++){
            int r = mt*16 + qrow + half*8;
            if (s0 + r < n){
                int bb = bl[r];
                float* dst = g_base + ((size_t)e*B + bb)*512;
                #pragma unroll
                for (int nt = 0; nt < 8; nt++){
                    int h = nb + nt*8 + qk2;
                    float2 o;
                    o.x = acc[mt][nt][half*2    ] + b1[e*512 + h];
                    o.y = acc[mt][nt][half*2 + 1] + b1[e*512 + h + 1];
                    *(float2*)(dst + h) = o;
                }
            }
        }
    }
}

// ---------------- K4: expert MLP via bf16 MMA (validated) ----------------
__global__ void __launch_bounds__(256, 1)
k_expert(const float* __restrict__ fut, const float* __restrict__ eps,
         const int* __restrict__ t, const float* __restrict__ b2){
    extern __shared__ char smraw[];
    __nv_bfloat16* nzs = (__nv_bfloat16*)smraw;       // 64 x 72
    __nv_bfloat16* w1s = nzs + 64*72;                 // 512 x 72 (reused as w2s)
    __nv_bfloat16* hss = w1s + 512*72;                // 64 x 520
    float* basev = (float*)(hss + 64*520);            // 512
    __shared__ float red[8];

    int p = blockIdx.x;
    int b, e;
    if (p < 24){ b = p / 6; e = p - b*6; }
    else       { b = p - 20; e = g_sel[p - 20]; }
    int tid = threadIdx.x;
    bool do_loss  = (e == g_sel[b]);
    bool do_store = (b < 4);

    float ab = g_ab[t[b]];
    float sa = sqrtf(ab), sb = sqrtf(1.0f - ab);

    {
        int r = tid >> 2, c0 = (tid & 3) * 16;
        const float4* f4 = (const float4*)(fut + (size_t)b*4096 + r*64 + c0);
        const float4* e4 = (const float4*)(eps + (size_t)b*4096 + r*64 + c0);
        __nv_bfloat16* dst = nzs + r*72 + c0;
        #pragma unroll
        for (int i = 0; i < 4; i++){
            float4 vf = f4[i], ve = e4[i];
            *(__nv_bfloat162*)(dst + i*4    ) = __floats2bfloat162_rn(fmaf(sa,vf.x,sb*ve.x), fmaf(sa,vf.y,sb*ve.y));
            *(__nv_bfloat162*)(dst + i*4 + 2) = __floats2bfloat162_rn(fmaf(sa,vf.z,sb*ve.z), fmaf(sa,vf.w,sb*ve.w));
        }
    }
    #pragma unroll
    for (int i = 0; i < 2; i++){
        int h = tid + i*256;
        const int4* s4 = (const int4*)(c_W1n + ((size_t)e*512 + h)*64);
        int4* d4 = (int4*)(w1s + h*72);
        #pragma unroll
        for (int q = 0; q < 8; q++) d4[q] = s4[q];
    }
    basev[tid]       = g_base[((size_t)e*B + b)*512 + tid];
    basev[tid + 256] = g_base[((size_t)e*B + b)*512 + tid + 256];
    __syncthreads();

    int warp = tid >> 5, lane = tid & 31;
    int qrow = lane >> 2, qk2 = (lane & 3) * 2;
    int m0 = (warp >> 2) * 32;
    int n0 = (warp & 3) * 128;

    {
        unsigned a[2][4][4];
        #pragma unroll
        for (int mt = 0; mt < 2; mt++)
            #pragma unroll
            for (int ks = 0; ks < 4; ks++){
                const __nv_bfloat16* ap = nzs + (m0 + mt*16 + qrow)*72 + ks*16 + qk2;
                a[mt][ks][0] = *(const unsigned*)(ap);
                a[mt][ks][1] = *(const unsigned*)(ap + 8*72);
                a[mt][ks][2] = *(const unsigned*)(ap + 8);
                a[mt][ks][3] = *(const unsigned*)(ap + 8*72 + 8);
            }
        #pragma unroll 4
        for (int nto = 0; nto < 16; nto++){
            int h8 = n0 + nto*8;
            float c0v[2][4];
            #pragma unroll
            for (int mt = 0; mt < 2; mt++)
                #pragma unroll
                for (int r = 0; r < 4; r++) c0v[mt][r] = 0.0f;
            #pragma unroll
            for (int ks = 0; ks < 4; ks++){
                const __nv_bfloat16* bp = w1s + (h8 + qrow)*72 + ks*16 + qk2;
                unsigned b0 = *(const unsigned*)(bp);
                unsigned b1v = *(const unsigned*)(bp + 8);
                mma16816(c0v[0], a[0][ks], b0, b1v);
                mma16816(c0v[1], a[1][ks], b0, b1v);
            }
            int h = h8 + qk2;
            float ba0 = basev[h], ba1 = basev[h+1];
            #pragma unroll
            for (int mt = 0; mt < 2; mt++){
                int r = m0 + mt*16 + qrow;
                *(__nv_bfloat162*)(hss + r*520 + h) =
                    __floats2bfloat162_rn(gelu_fast(c0v[mt][0] + ba0), gelu_fast(c0v[mt][1] + ba1));
                *(__nv_bfloat162*)(hss + (r+8)*520 + h) =
                    __floats2bfloat162_rn(gelu_fast(c0v[mt][2] + ba0), gelu_fast(c0v[mt][3] + ba1));
            }
        }
    }
    __syncthreads();

    __nv_bfloat16* w2s = w1s;
    {
        int f = tid >> 2, seg = tid & 3;
        const int4* s4 = (const int4*)(c_W2t + ((size_t)e*64 + f)*512) + seg*16;
        int4* d4 = (int4*)(w2s + f*520) + seg*16;
        #pragma unroll
        for (int q = 0; q < 16; q++) d4[q] = s4[q];
    }
    __syncthreads();

    int f0 = (warp & 3) * 16;
    float acc[2][2][4];
    #pragma unroll
    for (int mt = 0; mt < 2; mt++)
        #pragma unroll
        for (int nt = 0; nt < 2; nt++)
            #pragma unroll
            for (int r = 0; r < 4; r++) acc[mt][nt][r] = 0.0f;

    #pragma unroll 4
    for (int ks = 0; ks < 32; ks++){
        unsigned a[2][4];
        #pragma unroll
        for (int mt = 0; mt < 2; mt++){
            const __nv_bfloat16* ap = hss + (m0 + mt*16 + qrow)*520 + ks*16 + qk2;
            a[mt][0] = *(const unsigned*)(ap);
            a[mt][1] = *(const unsigned*)(ap + 8*520);
            a[mt][2] = *(const unsigned*)(ap + 8);
            a[mt][3] = *(const unsigned*)(ap + 8*520 + 8);
        }
        #pragma unroll
        for (int nt = 0; nt < 2; nt++){
            const __nv_bfloat16* bp = w2s + (f0 + nt*8 + qrow)*520 + ks*16 + qk2;
            unsigned b0 = *(const unsigned*)(bp);
            unsigned b1v = *(const unsigned*)(bp + 8);
            mma16816(acc[0][nt], a[0], b0, b1v);
            mma16816(acc[1][nt], a[1], b0, b1v);
        }
    }

    float lsum = 0.0f;
    #pragma unroll
    for (int mt = 0; mt < 2; mt++){
        #pragma unroll
        for (int nt = 0; nt < 2; nt++){
            int fcol = f0 + nt*8 + qk2;
            float bb0 = b2[e*64 + fcol], bb1 = b2[e*64 + fcol + 1];
            #pragma unroll
            for (int half = 0; half < 2; half++){
                int r = m0 + mt*16 + qrow + half*8;
                float o0 = acc[mt][nt][half*2    ] + bb0;
                float o1 = acc[mt][nt][half*2 + 1] + bb1;
                if (do_store){
                    float2 st; st.x = o0; st.y = o1;
                    *(float2*)&g_outsub[((e*4 + b)*64 + r)*64 + fcol] = st;
                }
                if (do_loss){
                    float2 ev = *(const float2*)&eps[(size_t)b*4096 + r*64 + fcol];
                    float d0 = o0 - ev.x, d1 = o1 - ev.y;
                    lsum += d0*d0 + d1*d1;
                }
            }
        }
    }

    if (do_loss){
        #pragma unroll
        for (int off = 16; off; off >>= 1) lsum += __shfl_xor_sync(0xffffffff, lsum, off);
        if (lane == 0) red[warp] = lsum;
        __syncthreads();
        if (tid == 0){
            float tot = 0.0f;
            #pragma unroll
            for (int w = 0; w < 8; w++) tot += red[w];
            g_loss[b] = tot * (1.0f/4096.0f);
        }
    }
}

// ---------------- K5a: parallel final reduction ----------------
#define FIN_BLKS 96
__global__ void k_final_partial(){
    int bid = blockIdx.x, tid = threadIdx.x;
    if (bid < 2){
        __shared__ float sh[13];
        if (tid < 13) sh[tid] = 0.0f;
        __syncthreads();
        const float PW[3] = {1.0f, 5.0f, 5.0f};
        int b = bid*256 + tid;
        int s = g_sel[b];
        atomicAdd(&sh[0], g_loss[b] * PW[s % 3]);
        atomicAdd(&sh[1 + s], 1.0f);
        #pragma unroll
        for (int e = 0; e < 6; e++) atomicAdd(&sh[7 + e], g_probs[b*NE + e]);
        __syncthreads();
        if (tid == 0) atomicAdd(&g_accL, sh[0]);
        if (tid < 6){
            atomicAdd(&g_cntF[tid],  sh[1 + tid]);
            atomicAdd(&g_psumE[tid], sh[7 + tid]);
        }
    } else {
        int nb = FIN_BLKS - 2;
        int idx0 = (bid - 2)*256 + tid;
        int stride = nb*256;
        const int pa[7] = {0,1,3,4,0,1,2};
        const int pb[7] = {1,2,4,5,3,4,5};
        float ch = 0.0f;
        for (int i = idx0; i < 16384; i += stride){
            #pragma unroll
            for (int q = 0; q < 7; q++){
                float d = g_outsub[pa[q]*16384 + i] - g_outsub[pb[q]*16384 + i];
                ch += d*d;
            }
        }
        float smv = 0.0f;
        for (int i = idx0; i < 96768; i += stride){
            int e  = i / 16128; int r  = i - e*16128;
            int s  = r / 4032;  int r2 = r - s*4032;
            int idx = (e*4 + s)*4096 + r2;
            float d = g_outsub[idx + 64] - g_outsub[idx];
            smv += d*d;
        }
        #pragma unroll
        for (int off = 16; off; off >>= 1){
            ch  += __shfl_xor_sync(0xffffffff, ch,  off);
            smv += __shfl_xor_sync(0xffffffff, smv, off);
        }
        if ((tid & 31) == 0){
            atomicAdd(&g_accC, ch);
            atomicAdd(&g_accS, smv);
        }
    }
}

// ---------------- K5b: final scalar ----------------
__global__ void k_final_sum(float* __restrict__ out){
    if (threadIdx.x == 0){
        float lb = 0.0f;
        #pragma unroll
        for (int e = 0; e < 6; e++)
            lb += (g_cntF[e] / 512.0f) * (g_psumE[e] / 512.0f);
        out[0] = g_accL / 512.0f
               + 0.01f * (g_accC / 16384.0f + 0.5f * g_accS / 16128.0f)
               + 0.06f * lb;
    }
}

// ---------------- launch ----------------
extern "C" void kernel_launch(void* const* d_in, const int* in_sizes, int n_in,
                              void* d_out, int out_size){
    const float* obs  = (const float*)d_in[0];
    const float* fut  = (const float*)d_in[1];
    const float* sc   = (const float*)d_in[2];
    const float* eps  = (const float*)d_in[3];
    const int*   phase= (const int*)  d_in[4];
    const int*   t    = (const int*)  d_in[5];
    const float* Wenc = (const float*)d_in[6];
    const float* benc = (const float*)d_in[7];
    const float* Wstat= (const float*)d_in[8];
    const float* Wr   = (const float*)d_in[9];
    const float* br   = (const float*)d_in[10];
    const float* W1   = (const float*)d_in[11];
    const float* b1   = (const float*)d_in[12];
    const float* W2   = (const float*)d_in[13];
    const float* b2   = (const float*)d_in[14];

    const int SMEM_CTX  = (256*APAD + 128*APAD)*2 + 2*128*4;
    const int SMEM_BASE = (32*1032 + 512*72)*2 + 32*4;
    const int SMEM_EXP  = (64*72 + 512*72 + 64*520)*2 + 512*4;

    static bool once = false;
    static cudaStream_t s2;
    static cudaEvent_t evFork, evJoin;
    if (!once){
        cudaFuncSetAttribute(k_ctx_mma, cudaFuncAttributeMaxDynamicSharedMemorySize, SMEM_CTX);
        cudaFuncSetAttribute(k_base,    cudaFuncAttributeMaxDynamicSharedMemorySize, SMEM_BASE);
        cudaFuncSetAttribute(k_expert,  cudaFuncAttributeMaxDynamicSharedMemorySize, SMEM_EXP);
        cudaStreamCreateWithFlags(&s2, cudaStreamNonBlocking);
        cudaEventCreateWithFlags(&evFork, cudaEventDisableTiming);
        cudaEventCreateWithFlags(&evJoin, cudaEventDisableTiming);
        once = true;
    }

    // fork: side stream does init/temb/converts while main stream runs ctx GEMM
    cudaEventRecord(evFork, 0);
    cudaStreamWaitEvent(s2, evFork, 0);
    k_init      <<<1, 32, 0, s2>>>();
    k_temb      <<<B, 256, 0, s2>>>(t);
    k_convert_w1<<<dim3(16, 34, NE), 256, 0, s2>>>(W1);
    k_convert_w2<<<dim3(2, 16, NE), 256, 0, s2>>>(W2);
    cudaEventRecord(evJoin, s2);

    k_ctx_mma   <<<dim3(4, B), 512, SMEM_CTX>>>(obs, sc, Wenc, benc, Wstat);

    // join before router (needs g_cnt zeroed) and downstream consumers
    cudaStreamWaitEvent(0, evJoin, 0);

    k_router       <<<64, 256>>>(Wr, br, phase);
    k_base         <<<dim3(NE, 16), 256, SMEM_BASE>>>(b1);
    k_expert       <<<NPAIR, 256, SMEM_EXP>>>(fut, eps, t, b2);
    k_final_partial<<<FIN_BLKS, 256>>>();
    k_final_sum    <<<1, 32>>>((float*)d_out);
}

// round 7
// speedup vs baseline: 2.8085x; 1.1158x over previous
#include <cuda_runtime.h>
#include <cuda_bf16.h>
#include <math.h>

#define B   512
#define TP  256
#define DM  512
#define DS  32
#define NE  6
#define NPAIR 532

// ---------------- device scratch ----------------
__device__ float g_ab[1000];
__device__ float g_gctx[B*DM];
__device__ float g_temb[B*DM];
__device__ float g_probs[B*NE];
__device__ int   g_sel[B];
__device__ float g_loss[B];
__device__ float g_outsub[NE*4*64*64];
__device__ int   g_cnt[NE];
__device__ int   g_list[NE*512];
__device__ float g_base[NE*B*512];
__device__ __nv_bfloat16 c_W1n[NE*512*64];
__device__ __nv_bfloat16 c_W1b[(size_t)NE*512*1024];
__device__ __nv_bfloat16 c_W2t[NE*64*512];
__device__ float g_accL, g_accC, g_accS;
__device__ float g_psumE[NE];
__device__ float g_cntF[NE];

__device__ __forceinline__ float gelu_fast(float x){
    float s = x*x;
    float p = x * fmaf(s, 0.044715f, 1.0f);
    float argv = p * -2.3022083f;
    float e;
    asm("ex2.approx.f32 %0, %1;" : "=f"(e) : "f"(argv));
    float r;
    asm("rcp.approx.f32 %0, %1;" : "=f"(r) : "f"(e + 1.0f));
    return x * r;
}

__device__ __forceinline__ void mma16816(float* c, const unsigned* a, unsigned b0, unsigned b1){
    asm("mma.sync.aligned.m16n8k16.row.col.f32.bf16.bf16.f32 "
        "{%0,%1,%2,%3}, {%4,%5,%6,%7}, {%8,%9}, {%0,%1,%2,%3};"
        : "+f"(c[0]), "+f"(c[1]), "+f"(c[2]), "+f"(c[3])
        : "r"(a[0]), "r"(a[1]), "r"(a[2]), "r"(a[3]), "r"(b0), "r"(b1));
}

// ---------------- K0 ----------------
__global__ void k_init(){
    int tid = threadIdx.x;
    if (tid < NE){ g_cnt[tid] = 0; g_psumE[tid] = 0.0f; g_cntF[tid] = 0.0f; }
    if (tid == 6){ g_accL = 0.0f; g_accC = 0.0f; g_accS = 0.0f; }
    if (tid == 0){
        float ab = 1.0f;
        const float step = (0.02f - 0.0001f) / 999.0f;
        for (int i = 0; i < 1000; i++){
            float beta = 0.0001f + step * (float)i;
            ab *= (1.0f - beta);
            g_ab[i] = ab;
        }
    }
}

// ---------------- K1 ----------------
__global__ void k_temb(const int* __restrict__ t){
    int b = blockIdx.x;
    float tv = (float)t[b];
    for (int j = threadIdx.x; j < DM; j += blockDim.x){
        int i = (j < 256) ? j : (j - 256);
        float freq = expf(-9.210340371976184f * (float)i / 256.0f);
        float a = tv * freq;
        g_temb[b*DM + j] = (j < 256) ? sinf(a) : cosf(a);
    }
}

// ---------------- converts ----------------
__global__ void k_convert_w1(const float* __restrict__ W1){
    __shared__ float sm[32][33];
    int e = blockIdx.z, kt = blockIdx.y, ht = blockIdx.x;
    int tid = threadIdx.x;
    int i = tid >> 3, j4 = (tid & 7) * 4;
    float4 v = *(const float4*)&W1[((size_t)e*1088 + kt*32 + i)*512 + ht*32 + j4];
    sm[i][j4] = v.x; sm[i][j4+1] = v.y; sm[i][j4+2] = v.z; sm[i][j4+3] = v.w;
    __syncthreads();
    int h = ht*32 + i;
    int k = kt*32 + j4;
    __nv_bfloat162 p0 = __floats2bfloat162_rn(sm[j4][i],   sm[j4+1][i]);
    __nv_bfloat162 p1 = __floats2bfloat162_rn(sm[j4+2][i], sm[j4+3][i]);
    __nv_bfloat16* dst;
    if (kt < 2) dst = c_W1n + ((size_t)e*512 + h)*64 + k;
    else        dst = c_W1b + ((size_t)e*512 + h)*1024 + (k - 64);
    *(__nv_bfloat162*)dst       = p0;
    *(__nv_bfloat162*)(dst + 2) = p1;
}

__global__ void k_convert_w2(const float* __restrict__ W2){
    __shared__ float sm[32][33];
    int e = blockIdx.z, ht = blockIdx.y, ft = blockIdx.x;
    int tid = threadIdx.x;
    int i = tid >> 3, j4 = (tid & 7) * 4;
    float4 v = *(const float4*)&W2[((size_t)e*512 + ht*32 + i)*64 + ft*32 + j4];
    sm[i][j4] = v.x; sm[i][j4+1] = v.y; sm[i][j4+2] = v.z; sm[i][j4+3] = v.w;
    __syncthreads();
    int f = ft*32 + i;
    int h = ht*32 + j4;
    __nv_bfloat162 p0 = __floats2bfloat162_rn(sm[j4][i],   sm[j4+1][i]);
    __nv_bfloat162 p1 = __floats2bfloat162_rn(sm[j4+2][i], sm[j4+3][i]);
    __nv_bfloat16* dst = c_W2t + ((size_t)e*64 + f)*512 + h;
    *(__nv_bfloat162*)dst       = p0;
    *(__nv_bfloat162*)(dst + 2) = p1;
}

// ---------------- K2: ctx GEMM (validated) ----------------
#define APAD 72
__global__ void __launch_bounds__(512, 1)
k_ctx_mma(const float* __restrict__ obs, const float* __restrict__ sc,
          const float* __restrict__ Wenc, const float* __restrict__ benc,
          const float* __restrict__ Wstat){
    extern __shared__ char smraw[];
    __nv_bfloat16* As = (__nv_bfloat16*)smraw;
    __nv_bfloat16* Bs = As + 256*APAD;
    float* pre    = (float*)(Bs + 128*APAD);
    float* colsum = pre + 128;

    int b  = blockIdx.y;
    int n0 = blockIdx.x * 128;
    int tid = threadIdx.x;

    {
        int row = tid >> 1;
        int c0  = (tid & 1) * 32;
        const float4* src = (const float4*)(obs + (size_t)b*TP*64 + row*64 + c0);
        __nv_bfloat16* arow = As + row*APAD + c0;
        #pragma unroll
        for (int i = 0; i < 8; i++){
            float4 v = src[i];
            *(__nv_bfloat162*)(arow + i*4    ) = __floats2bfloat162_rn(v.x, v.y);
            *(__nv_bfloat162*)(arow + i*4 + 2) = __floats2bfloat162_rn(v.z, v.w);
        }
    }
    {
        int j  = tid >> 2;
        int kq = (tid & 3) * 16;
        int jg = n0 + j;
        #pragma unroll
        for (int i = 0; i < 16; i++)
            Bs[j*APAD + kq + i] = __float2bfloat16_rn(Wenc[(kq + i)*DM + jg]);
    }
    if (tid < 128){
        int jg = n0 + tid;
        float acc = benc[jg];
        #pragma unroll
        for (int k = 0; k < 32; k++) acc = fmaf(sc[b*DS + k], Wstat[k*DM + jg], acc);
        pre[tid] = acc;
        colsum[tid] = 0.0f;
    }
    __syncthreads();

    int warp = tid >> 5, lane = tid & 31;
    int m0 = (warp >> 1) * 32;
    int nb = (warp & 1) * 64;
    int qrow = lane >> 2;
    int qk2  = (lane & 3) * 2;

    float c[2][8][4];
    #pragma unroll
    for (int mt = 0; mt < 2; mt++)
        #pragma unroll
        for (int nt = 0; nt < 8; nt++)
            #pragma unroll
            for (int r = 0; r < 4; r++) c[mt][nt][r] = 0.0f;

    #pragma unroll
    for (int kk = 0; kk < 4; kk++){
        unsigned a[2][4];
        #pragma unroll
        for (int mt = 0; mt < 2; mt++){
            const __nv_bfloat16* ap = As + (m0 + mt*16 + qrow)*APAD + kk*16 + qk2;
            a[mt][0] = *(const unsigned*)(ap);
            a[mt][1] = *(const unsigned*)(ap + 8*APAD);
            a[mt][2] = *(const unsigned*)(ap + 8);
            a[mt][3] = *(const unsigned*)(ap + 8*APAD + 8);
        }
        #pragma unroll
        for (int nt = 0; nt < 8; nt++){
            const __nv_bfloat16* bp = Bs + (nb + nt*8 + qrow)*APAD + kk*16 + qk2;
            unsigned b0 = *(const unsigned*)(bp);
            unsigned b1 = *(const unsigned*)(bp + 8);
            mma16816(c[0][nt], a[0], b0, b1);
            mma16816(c[1][nt], a[1], b0, b1);
        }
    }

    #pragma unroll
    for (int nt = 0; nt < 8; nt++){
        int jl = nb + nt*8 + qk2;
        float p0 = pre[jl], p1 = pre[jl + 1];
        float s0 = 0.0f, s1 = 0.0f;
        #pragma unroll
        for (int mt = 0; mt < 2; mt++){
            s0 += gelu_fast(c[mt][nt][0] + p0) + gelu_fast(c[mt][nt][2] + p0);
            s1 += gelu_fast(c[mt][nt][1] + p1) + gelu_fast(c[mt][nt][3] + p1);
        }
        #pragma unroll
        for (int off = 16; off >= 4; off >>= 1){
            s0 += __shfl_xor_sync(0xffffffff, s0, off);
            s1 += __shfl_xor_sync(0xffffffff, s1, off);
        }
        if (qrow == 0){
            atomicAdd(&colsum[jl    ], s0);
            atomicAdd(&colsum[jl + 1], s1);
        }
    }
    __syncthreads();

    if (tid < 128)
        g_gctx[b*DM + n0 + tid] = colsum[tid] * (1.0f/256.0f);
}

// ---------------- K3: router ----------------
__global__ void k_router(const float* __restrict__ Wr, const float* __restrict__ br,
                         const int* __restrict__ phase){
    __shared__ float wsh[DM*NE];
    int tid = threadIdx.x;
    for (int i = tid; i < DM*NE/2; i += 256)
        ((float2*)wsh)[i] = ((const float2*)Wr)[i];
    __syncthreads();

    int warp = tid >> 5, lane = tid & 31;
    int b = blockIdx.x*8 + warp;
    float p[6] = {0,0,0,0,0,0};
    #pragma unroll
    for (int it = 0; it < 4; it++){
        int k0 = it*128 + lane*4;
        float4 g = *(const float4*)&g_gctx[b*DM + k0];
        #pragma unroll
        for (int j = 0; j < 4; j++){
            float gv = (&g.x)[j];
            const float* w = wsh + (k0 + j)*NE;
            #pragma unroll
            for (int e = 0; e < 6; e++) p[e] = fmaf(gv, w[e], p[e]);
        }
    }
    #pragma unroll
    for (int off = 16; off; off >>= 1){
        #pragma unroll
        for (int e = 0; e < 6; e++) p[e] += __shfl_xor_sync(0xffffffff, p[e], off);
    }
    if (lane == 0){
        float l[6], pr[6];
        #pragma unroll
        for (int e = 0; e < 6; e++) l[e] = p[e] + br[e];
        float m = l[0];
        #pragma unroll
        for (int e = 1; e < 6; e++) m = fmaxf(m, l[e]);
        float s = 0.0f;
        #pragma unroll
        for (int e = 0; e < 6; e++){ pr[e] = expf(l[e] - m); s += pr[e]; }
        float inv = 1.0f / s;
        #pragma unroll
        for (int e = 0; e < 6; e++){ pr[e] *= inv; g_probs[b*NE + e] = pr[e]; }
        int pl = phase[b];
        int sel = pl + ((pr[pl+3] > pr[pl]) ? 3 : 0);
        g_sel[b] = sel;
        if (b < 4){
            #pragma unroll
            for (int e = 0; e < 6; e++){
                int idx = atomicAdd(&g_cnt[e], 1);
                g_list[e*512 + idx] = b;
            }
        } else {
            int idx = atomicAdd(&g_cnt[sel], 1);
            g_list[sel*512 + idx] = b;
        }
    }
}

// ---------------- K3c: base via bf16 MMA, B direct from global ----------------
__global__ void __launch_bounds__(256, 1)
k_base(const float* __restrict__ b1){
    extern __shared__ char smraw[];
    __nv_bfloat16* As = (__nv_bfloat16*)smraw;   // 32 x 1032
    int* bl = (int*)(As + 32*1032);              // 32

    int e = blockIdx.x, tile = blockIdx.y;
    int n = g_cnt[e], s0 = tile*32;
    if (s0 >= n) return;
    int tid = threadIdx.x;

    if (tid < 32){
        int s = s0 + tid;
        bl[tid] = (s < n) ? g_list[e*512 + s] : g_list[e*512];
    }
    __syncthreads();

    {
        int r = tid >> 3, seg = tid & 7;
        int bb = bl[r];
        const float4* src = (const float4*)((seg < 4)
            ? (g_gctx + bb*512 + seg*128)
            : (g_temb + bb*512 + seg*128 - 512));
        __nv_bfloat16* dst = As + r*1032 + seg*128;
        #pragma unroll
        for (int i = 0; i < 32; i++){
            float4 v = src[i];
            *(__nv_bfloat162*)(dst + i*4    ) = __floats2bfloat162_rn(v.x, v.y);
            *(__nv_bfloat162*)(dst + i*4 + 2) = __floats2bfloat162_rn(v.z, v.w);
        }
    }
    __syncthreads();

    int warp = tid >> 5, lane = tid & 31;
    int qrow = lane >> 2;
    int qk2 = (lane & 3) * 2;
    int nb = warp * 64;
    const __nv_bfloat16* W1bE = c_W1b + (size_t)e*512*1024;

    float acc[2][8][4];
    #pragma unroll
    for (int mt = 0; mt < 2; mt++)
        #pragma unroll
        for (int nt = 0; nt < 8; nt++)
            #pragma unroll
            for (int r = 0; r < 4; r++) acc[mt][nt][r] = 0.0f;

    for (int kc = 0; kc < 16; kc++){
        #pragma unroll
        for (int ks = 0; ks < 4; ks++){
            int kof = kc*64 + ks*16 + qk2;
            unsigned a[2][4];
            #pragma unroll
            for (int mt = 0; mt < 2; mt++){
                const __nv_bfloat16* ap = As + (mt*16 + qrow)*1032 + kof;
                a[mt][0] = *(const unsigned*)(ap);
                a[mt][1] = *(const unsigned*)(ap + 8*1032);
                a[mt][2] = *(const unsigned*)(ap + 8);
                a[mt][3] = *(const unsigned*)(ap + 8*1032 + 8);
            }
            #pragma unroll
            for (int nt = 0; nt < 8; nt++){
                const __nv_bfloat16* bp = W1bE + (size_t)(nb + nt*8 + qrow)*1024 + kof;
                unsigned b0 = *(const unsigned*)(bp);
                unsigned b1v = *(const unsigned*)(bp + 8);
                mma16816(acc[0][nt], a[0], b0, b1v);
                mma16816(acc[1][nt], a[1], b0, b1v);
            }
        }
    }

    #pragma unroll
    for (int mt = 0; mt < 2; mt++){
        #pragma unroll
        for (int half = 0; half < 2; half++){
            int r = mt*16 + qrow + half*8;
            if (s0 + r < n){
                int bb = bl[r];
                float* dst = g_base + ((size_t)e*B + bb)*512;
                #pragma unroll
                for (int nt = 0; nt < 8; nt++){
                    int h = nb + nt*8 + qk2;
                    float2 o;
                    o.x = acc[mt][nt][half*2    ] + b1[e*512 + h];
                    o.y = acc[mt][nt][half*2 + 1] + b1[e*512 + h + 1];
                    *(float2*)(dst + h) = o;
                }
            }
        }
    }
}

// ---------------- K4: expert MLP, B direct from global, 2 blocks/SM ----------------
__global__ void __launch_bounds__(256, 2)
k_expert(const float* __restrict__ fut, const float* __restrict__ eps,
         const int* __restrict__ t, const float* __restrict__ b2){
    extern __shared__ char smraw[];
    __nv_bfloat16* nzs = (__nv_bfloat16*)smraw;       // 64 x 72
    __nv_bfloat16* hss = nzs + 64*72;                 // 64 x 520
    float* basev = (float*)(hss + 64*520);            // 512
    __shared__ float red[8];

    int p = blockIdx.x;
    int b, e;
    if (p < 24){ b = p / 6; e = p - b*6; }
    else       { b = p - 20; e = g_sel[p - 20]; }
    int tid = threadIdx.x;
    bool do_loss  = (e == g_sel[b]);
    bool do_store = (b < 4);

    float ab = g_ab[t[b]];
    float sa = sqrtf(ab), sb = sqrtf(1.0f - ab);

    {
        int r = tid >> 2, c0 = (tid & 3) * 16;
        const float4* f4 = (const float4*)(fut + (size_t)b*4096 + r*64 + c0);
        const float4* e4 = (const float4*)(eps + (size_t)b*4096 + r*64 + c0);
        __nv_bfloat16* dst = nzs + r*72 + c0;
        #pragma unroll
        for (int i = 0; i < 4; i++){
            float4 vf = f4[i], ve = e4[i];
            *(__nv_bfloat162*)(dst + i*4    ) = __floats2bfloat162_rn(fmaf(sa,vf.x,sb*ve.x), fmaf(sa,vf.y,sb*ve.y));
            *(__nv_bfloat162*)(dst + i*4 + 2) = __floats2bfloat162_rn(fmaf(sa,vf.z,sb*ve.z), fmaf(sa,vf.w,sb*ve.w));
        }
    }
    basev[tid]       = g_base[((size_t)e*B + b)*512 + tid];
    basev[tid + 256] = g_base[((size_t)e*B + b)*512 + tid + 256];
    __syncthreads();

    int warp = tid >> 5, lane = tid & 31;
    int qrow = lane >> 2, qk2 = (lane & 3) * 2;

    // ---- phase1: warp owns n-slice of 64 h, full M=64 ----
    {
        int n0 = warp * 64;
        const __nv_bfloat16* W1nE = c_W1n + (size_t)e*512*64;

        unsigned a[4][4][4];
        #pragma unroll
        for (int mt = 0; mt < 4; mt++)
            #pragma unroll
            for (int ks = 0; ks < 4; ks++){
                const __nv_bfloat16* ap = nzs + (mt*16 + qrow)*72 + ks*16 + qk2;
                a[mt][ks][0] = *(const unsigned*)(ap);
                a[mt][ks][1] = *(const unsigned*)(ap + 8*72);
                a[mt][ks][2] = *(const unsigned*)(ap + 8);
                a[mt][ks][3] = *(const unsigned*)(ap + 8*72 + 8);
            }

        #pragma unroll
        for (int nto = 0; nto < 8; nto++){
            int h8 = n0 + nto*8;
            unsigned bfr[4][2];
            #pragma unroll
            for (int ks = 0; ks < 4; ks++){
                const __nv_bfloat16* bp = W1nE + (h8 + qrow)*64 + ks*16 + qk2;
                bfr[ks][0] = *(const unsigned*)(bp);
                bfr[ks][1] = *(const unsigned*)(bp + 8);
            }
            float c0v[4][4];
            #pragma unroll
            for (int mt = 0; mt < 4; mt++)
                #pragma unroll
                for (int r = 0; r < 4; r++) c0v[mt][r] = 0.0f;
            #pragma unroll
            for (int ks = 0; ks < 4; ks++){
                #pragma unroll
                for (int mt = 0; mt < 4; mt++)
                    mma16816(c0v[mt], a[mt][ks], bfr[ks][0], bfr[ks][1]);
            }
            int h = h8 + qk2;
            float ba0 = basev[h], ba1 = basev[h+1];
            #pragma unroll
            for (int mt = 0; mt < 4; mt++){
                int r = mt*16 + qrow;
                *(__nv_bfloat162*)(hss + r*520 + h) =
                    __floats2bfloat162_rn(gelu_fast(c0v[mt][0] + ba0), gelu_fast(c0v[mt][1] + ba1));
                *(__nv_bfloat162*)(hss + (r+8)*520 + h) =
                    __floats2bfloat162_rn(gelu_fast(c0v[mt][2] + ba0), gelu_fast(c0v[mt][3] + ba1));
            }
        }
    }
    __syncthreads();

    // ---- phase2: warp owns f-slice of 8, full M=64, K=512 ----
    int f0 = warp * 8;
    const __nv_bfloat16* W2tE = c_W2t + (size_t)e*64*512;

    float acc[4][4];
    #pragma unroll
    for (int mt = 0; mt < 4; mt++)
        #pragma unroll
        for (int r = 0; r < 4; r++) acc[mt][r] = 0.0f;

    #pragma unroll 8
    for (int ks = 0; ks < 32; ks++){
        const __nv_bfloat16* bp = W2tE + (f0 + qrow)*512 + ks*16 + qk2;
        unsigned b0 = *(const unsigned*)(bp);
        unsigned b1v = *(const unsigned*)(bp + 8);
        #pragma unroll
        for (int mt = 0; mt < 4; mt++){
            const __nv_bfloat16* ap = hss + (mt*16 + qrow)*520 + ks*16 + qk2;
            unsigned a2[4];
            a2[0] = *(const unsigned*)(ap);
            a2[1] = *(const unsigned*)(ap + 8*520);
            a2[2] = *(const unsigned*)(ap + 8);
            a2[3] = *(const unsigned*)(ap + 8*520 + 8);
            mma16816(acc[mt], a2, b0, b1v);
        }
    }

    float lsum = 0.0f;
    int fcol = f0 + qk2;
    float bb0 = b2[e*64 + fcol], bb1 = b2[e*64 + fcol + 1];
    #pragma unroll
    for (int mt = 0; mt < 4; mt++){
        #pragma unroll
        for (int half = 0; half < 2; half++){
            int r = mt*16 + qrow + half*8;
            float o0 = acc[mt][half*2    ] + bb0;
            float o1 = acc[mt][half*2 + 1] + bb1;
            if (do_store){
                float2 st; st.x = o0; st.y = o1;
                *(float2*)&g_outsub[((e*4 + b)*64 + r)*64 + fcol] = st;
            }
            if (do_loss){
                float2 ev = *(const float2*)&eps[(size_t)b*4096 + r*64 + fcol];
                float d0 = o0 - ev.x, d1 = o1 - ev.y;
                lsum += d0*d0 + d1*d1;
            }
        }
    }

    if (do_loss){
        #pragma unroll
        for (int off = 16; off; off >>= 1) lsum += __shfl_xor_sync(0xffffffff, lsum, off);
        if (lane == 0) red[warp] = lsum;
        __syncthreads();
        if (tid == 0){
            float tot = 0.0f;
            #pragma unroll
            for (int w = 0; w < 8; w++) tot += red[w];
            g_loss[b] = tot * (1.0f/4096.0f);
        }
    }
}

// ---------------- K5a ----------------
#define FIN_BLKS 96
__global__ void k_final_partial(){
    int bid = blockIdx.x, tid = threadIdx.x;
    if (bid < 2){
        __shared__ float sh[13];
        if (tid < 13) sh[tid] = 0.0f;
        __syncthreads();
        const float PW[3] = {1.0f, 5.0f, 5.0f};
        int b = bid*256 + tid;
        int s = g_sel[b];
        atomicAdd(&sh[0], g_loss[b] * PW[s % 3]);
        atomicAdd(&sh[1 + s], 1.0f);
        #pragma unroll
        for (int e = 0; e < 6; e++) atomicAdd(&sh[7 + e], g_probs[b*NE + e]);
        __syncthreads();
        if (tid == 0) atomicAdd(&g_accL, sh[0]);
        if (tid < 6){
            atomicAdd(&g_cntF[tid],  sh[1 + tid]);
            atomicAdd(&g_psumE[tid], sh[7 + tid]);
        }
    } else {
        int nb = FIN_BLKS - 2;
        int idx0 = (bid - 2)*256 + tid;
        int stride = nb*256;
        const int pa[7] = {0,1,3,4,0,1,2};
        const int pb[7] = {1,2,4,5,3,4,5};
        float ch = 0.0f;
        for (int i = idx0; i < 16384; i += stride){
            #pragma unroll
            for (int q = 0; q < 7; q++){
                float d = g_outsub[pa[q]*16384 + i] - g_outsub[pb[q]*16384 + i];
                ch += d*d;
            }
        }
        float smv = 0.0f;
        for (int i = idx0; i < 96768; i += stride){
            int e  = i / 16128; int r  = i - e*16128;
            int s  = r / 4032;  int r2 = r - s*4032;
            int idx = (e*4 + s)*4096 + r2;
            float d = g_outsub[idx + 64] - g_outsub[idx];
            smv += d*d;
        }
        #pragma unroll
        for (int off = 16; off; off >>= 1){
            ch  += __shfl_xor_sync(0xffffffff, ch,  off);
            smv += __shfl_xor_sync(0xffffffff, smv, off);
        }
        if ((tid & 31) == 0){
            atomicAdd(&g_accC, ch);
            atomicAdd(&g_accS, smv);
        }
    }
}

// ---------------- K5b ----------------
__global__ void k_final_sum(float* __restrict__ out){
    if (threadIdx.x == 0){
        float lb = 0.0f;
        #pragma unroll
        for (int e = 0; e < 6; e++)
            lb += (g_cntF[e] / 512.0f) * (g_psumE[e] / 512.0f);
        out[0] = g_accL / 512.0f
               + 0.01f * (g_accC / 16384.0f + 0.5f * g_accS / 16128.0f)
               + 0.06f * lb;
    }
}

// ---------------- launch ----------------
extern "C" void kernel_launch(void* const* d_in, const int* in_sizes, int n_in,
                              void* d_out, int out_size){
    const float* obs  = (const float*)d_in[0];
    const float* fut  = (const float*)d_in[1];
    const float* sc   = (const float*)d_in[2];
    const float* eps  = (const float*)d_in[3];
    const int*   phase= (const int*)  d_in[4];
    const int*   t    = (const int*)  d_in[5];
    const float* Wenc = (const float*)d_in[6];
    const float* benc = (const float*)d_in[7];
    const float* Wstat= (const float*)d_in[8];
    const float* Wr   = (const float*)d_in[9];
    const float* br   = (const float*)d_in[10];
    const float* W1   = (const float*)d_in[11];
    const float* b1   = (const float*)d_in[12];
    const float* W2   = (const float*)d_in[13];
    const float* b2   = (const float*)d_in[14];

    const int SMEM_CTX  = (256*APAD + 128*APAD)*2 + 2*128*4;
    const int SMEM_BASE = 32*1032*2 + 128;
    const int SMEM_EXP  = (64*72 + 64*520)*2 + 512*4;   // 77,824 B

    static bool once = false;
    static cudaStream_t s2;
    static cudaEvent_t evFork, evJoin;
    if (!once){
        cudaFuncSetAttribute(k_ctx_mma, cudaFuncAttributeMaxDynamicSharedMemorySize, SMEM_CTX);
        cudaFuncSetAttribute(k_base,    cudaFuncAttributeMaxDynamicSharedMemorySize, SMEM_BASE);
        cudaFuncSetAttribute(k_expert,  cudaFuncAttributeMaxDynamicSharedMemorySize, SMEM_EXP);
        cudaStreamCreateWithFlags(&s2, cudaStreamNonBlocking);
        cudaEventCreateWithFlags(&evFork, cudaEventDisableTiming);
        cudaEventCreateWithFlags(&evJoin, cudaEventDisableTiming);
        once = true;
    }

    cudaEventRecord(evFork, 0);
    cudaStreamWaitEvent(s2, evFork, 0);
    k_init      <<<1, 32, 0, s2>>>();
    k_temb      <<<B, 256, 0, s2>>>(t);
    k_convert_w1<<<dim3(16, 34, NE), 256, 0, s2>>>(W1);
    k_convert_w2<<<dim3(2, 16, NE), 256, 0, s2>>>(W2);
    cudaEventRecord(evJoin, s2);

    k_ctx_mma   <<<dim3(4, B), 512, SMEM_CTX>>>(obs, sc, Wenc, benc, Wstat);

    cudaStreamWaitEvent(0, evJoin, 0);

    k_router       <<<64, 256>>>(Wr, br, phase);
    k_base         <<<dim3(NE, 16), 256, SMEM_BASE>>>(b1);
    k_expert       <<<NPAIR, 256, SMEM_EXP>>>(fut, eps, t, b2);
    k_final_partial<<<FIN_BLKS, 256>>>();
    k_final_sum    <<<1, 32>>>((float*)d_out);
}

// round 8
// speedup vs baseline: 3.1692x; 1.1284x over previous
#include <cuda_runtime.h>
#include <cuda_bf16.h>
#include <math.h>

#define B   512
#define TP  256
#define DM  512
#define DS  32
#define NE  6
#define NPAIR 532

// ---------------- device scratch ----------------
__device__ float g_ab[1000];
__device__ float g_gctx[B*DM];
__device__ float g_temb[B*DM];
__device__ float g_probs[B*NE];
__device__ int   g_sel[B];
__device__ float g_loss[B];
__device__ float g_outsub[NE*4*64*64];
__device__ int   g_cnt[NE];
__device__ int   g_list[NE*512];
__device__ float g_base[NE*B*512];
__device__ __nv_bfloat16 c_Wenc[DM*64];
__device__ __nv_bfloat16 c_W1n[NE*512*64];
__device__ __nv_bfloat16 c_W1b[(size_t)NE*512*1024];
__device__ __nv_bfloat16 c_W2t[NE*64*512];
__device__ float g_accL, g_accC, g_accS;
__device__ float g_psumE[NE];
__device__ float g_cntF[NE];

__device__ __forceinline__ float gelu_fast(float x){
    float s = x*x;
    float p = x * fmaf(s, 0.044715f, 1.0f);
    float argv = p * -2.3022083f;
    float e;
    asm("ex2.approx.f32 %0, %1;" : "=f"(e) : "f"(argv));
    float r;
    asm("rcp.approx.f32 %0, %1;" : "=f"(r) : "f"(e + 1.0f));
    return x * r;
}

__device__ __forceinline__ void mma16816(float* c, const unsigned* a, unsigned b0, unsigned b1){
    asm("mma.sync.aligned.m16n8k16.row.col.f32.bf16.bf16.f32 "
        "{%0,%1,%2,%3}, {%4,%5,%6,%7}, {%8,%9}, {%0,%1,%2,%3};"
        : "+f"(c[0]), "+f"(c[1]), "+f"(c[2]), "+f"(c[3])
        : "r"(a[0]), "r"(a[1]), "r"(a[2]), "r"(a[3]), "r"(b0), "r"(b1));
}

// ---------------- K0 ----------------
__global__ void k_init(){
    int tid = threadIdx.x;
    if (tid < NE){ g_cnt[tid] = 0; g_psumE[tid] = 0.0f; g_cntF[tid] = 0.0f; }
    if (tid == 6){ g_accL = 0.0f; g_accC = 0.0f; g_accS = 0.0f; }
    if (tid == 0){
        float ab = 1.0f;
        const float step = (0.02f - 0.0001f) / 999.0f;
        for (int i = 0; i < 1000; i++){
            float beta = 0.0001f + step * (float)i;
            ab *= (1.0f - beta);
            g_ab[i] = ab;
        }
    }
}

// ---------------- K1 ----------------
__global__ void k_temb(const int* __restrict__ t){
    int b = blockIdx.x;
    float tv = (float)t[b];
    for (int j = threadIdx.x; j < DM; j += blockDim.x){
        int i = (j < 256) ? j : (j - 256);
        float freq = expf(-9.210340371976184f * (float)i / 256.0f);
        float a = tv * freq;
        g_temb[b*DM + j] = (j < 256) ? sinf(a) : cosf(a);
    }
}

// ---------------- converts ----------------
__global__ void k_convert_wenc(const float* __restrict__ Wenc){
    int gid = blockIdx.x*256 + threadIdx.x;    // 1024 threads
    int n = gid >> 1, kh = (gid & 1) * 32;
    #pragma unroll
    for (int i = 0; i < 32; i++){
        int k = kh + i;
        c_Wenc[n*64 + k] = __float2bfloat16_rn(Wenc[k*DM + n]);
    }
}

__global__ void k_convert_w1(const float* __restrict__ W1){
    __shared__ float sm[32][33];
    int e = blockIdx.z, kt = blockIdx.y, ht = blockIdx.x;
    int tid = threadIdx.x;
    int i = tid >> 3, j4 = (tid & 7) * 4;
    float4 v = *(const float4*)&W1[((size_t)e*1088 + kt*32 + i)*512 + ht*32 + j4];
    sm[i][j4] = v.x; sm[i][j4+1] = v.y; sm[i][j4+2] = v.z; sm[i][j4+3] = v.w;
    __syncthreads();
    int h = ht*32 + i;
    int k = kt*32 + j4;
    __nv_bfloat162 p0 = __floats2bfloat162_rn(sm[j4][i],   sm[j4+1][i]);
    __nv_bfloat162 p1 = __floats2bfloat162_rn(sm[j4+2][i], sm[j4+3][i]);
    __nv_bfloat16* dst;
    if (kt < 2) dst = c_W1n + ((size_t)e*512 + h)*64 + k;
    else        dst = c_W1b + ((size_t)e*512 + h)*1024 + (k - 64);
    *(__nv_bfloat162*)dst       = p0;
    *(__nv_bfloat162*)(dst + 2) = p1;
}

__global__ void k_convert_w2(const float* __restrict__ W2){
    __shared__ float sm[32][33];
    int e = blockIdx.z, ht = blockIdx.y, ft = blockIdx.x;
    int tid = threadIdx.x;
    int i = tid >> 3, j4 = (tid & 7) * 4;
    float4 v = *(const float4*)&W2[((size_t)e*512 + ht*32 + i)*64 + ft*32 + j4];
    sm[i][j4] = v.x; sm[i][j4+1] = v.y; sm[i][j4+2] = v.z; sm[i][j4+3] = v.w;
    __syncthreads();
    int f = ft*32 + i;
    int h = ht*32 + j4;
    __nv_bfloat162 p0 = __floats2bfloat162_rn(sm[j4][i],   sm[j4+1][i]);
    __nv_bfloat162 p1 = __floats2bfloat162_rn(sm[j4+2][i], sm[j4+3][i]);
    __nv_bfloat16* dst = c_W2t + ((size_t)e*64 + f)*512 + h;
    *(__nv_bfloat162*)dst       = p0;
    *(__nv_bfloat162*)(dst + 2) = p1;
}

// ---------------- K2: fused ctx GEMM + router, one block per sample ----------------
#define APAD 72
__global__ void __launch_bounds__(512, 1)
k_ctx_fused(const float* __restrict__ obs, const float* __restrict__ sc,
            const float* __restrict__ benc, const float* __restrict__ Wstat,
            const float* __restrict__ Wr, const float* __restrict__ br,
            const int* __restrict__ phase){
    extern __shared__ char smraw[];
    __nv_bfloat16* As = (__nv_bfloat16*)smraw;     // 256 x 72 bf16
    float* pre  = (float*)(As + 256*APAD);          // 512
    float* gbuf = pre + 512;                        // 512

    int b = blockIdx.x;
    int tid = threadIdx.x;

    // obs -> As bf16
    {
        int row = tid >> 1;
        int c0  = (tid & 1) * 32;
        const float4* src = (const float4*)(obs + (size_t)b*TP*64 + row*64 + c0);
        __nv_bfloat16* arow = As + row*APAD + c0;
        #pragma unroll
        for (int i = 0; i < 8; i++){
            float4 v = src[i];
            *(__nv_bfloat162*)(arow + i*4    ) = __floats2bfloat162_rn(v.x, v.y);
            *(__nv_bfloat162*)(arow + i*4 + 2) = __floats2bfloat162_rn(v.z, v.w);
        }
    }
    // pre[j] = benc[j] + static @ Wstat
    {
        float acc = benc[tid];
        #pragma unroll
        for (int k = 0; k < 32; k++) acc = fmaf(sc[b*DS + k], Wstat[k*DM + tid], acc);
        pre[tid] = acc;
    }
    __syncthreads();

    int warp = tid >> 5, lane = tid & 31;
    int qrow = lane >> 2, qk2 = (lane & 3) * 2;
    int n0 = warp * 32;

    // B fragments direct from global (64 KB, L1-resident)
    unsigned bfr[4][4][2];
    #pragma unroll
    for (int nt = 0; nt < 4; nt++)
        #pragma unroll
        for (int ks = 0; ks < 4; ks++){
            const __nv_bfloat16* bp = c_Wenc + (n0 + nt*8 + qrow)*64 + ks*16 + qk2;
            bfr[nt][ks][0] = *(const unsigned*)(bp);
            bfr[nt][ks][1] = *(const unsigned*)(bp + 8);
        }
    float prev[4][2];
    #pragma unroll
    for (int nt = 0; nt < 4; nt++){
        prev[nt][0] = pre[n0 + nt*8 + qk2];
        prev[nt][1] = pre[n0 + nt*8 + qk2 + 1];
    }

    float s[4][2];
    #pragma unroll
    for (int nt = 0; nt < 4; nt++){ s[nt][0] = 0.0f; s[nt][1] = 0.0f; }

    // loop over M in chunks of 32 rows
    #pragma unroll 2
    for (int mc = 0; mc < 8; mc++){
        unsigned a[2][4][4];
        #pragma unroll
        for (int mt = 0; mt < 2; mt++)
            #pragma unroll
            for (int ks = 0; ks < 4; ks++){
                const __nv_bfloat16* ap = As + (mc*32 + mt*16 + qrow)*APAD + ks*16 + qk2;
                a[mt][ks][0] = *(const unsigned*)(ap);
                a[mt][ks][1] = *(const unsigned*)(ap + 8*APAD);
                a[mt][ks][2] = *(const unsigned*)(ap + 8);
                a[mt][ks][3] = *(const unsigned*)(ap + 8*APAD + 8);
            }
        float c[2][4][4];
        #pragma unroll
        for (int mt = 0; mt < 2; mt++)
            #pragma unroll
            for (int nt = 0; nt < 4; nt++)
                #pragma unroll
                for (int r = 0; r < 4; r++) c[mt][nt][r] = 0.0f;
        #pragma unroll
        for (int ks = 0; ks < 4; ks++)
            #pragma unroll
            for (int mt = 0; mt < 2; mt++)
                #pragma unroll
                for (int nt = 0; nt < 4; nt++)
                    mma16816(c[mt][nt], a[mt][ks], bfr[nt][ks][0], bfr[nt][ks][1]);
        #pragma unroll
        for (int mt = 0; mt < 2; mt++)
            #pragma unroll
            for (int nt = 0; nt < 4; nt++){
                s[nt][0] += gelu_fast(c[mt][nt][0] + prev[nt][0]) + gelu_fast(c[mt][nt][2] + prev[nt][0]);
                s[nt][1] += gelu_fast(c[mt][nt][1] + prev[nt][1]) + gelu_fast(c[mt][nt][3] + prev[nt][1]);
            }
    }

    // reduce over qrow lanes (8 rows x 4 lanes -> lanes 0..3 hold full col sums)
    #pragma unroll
    for (int off = 16; off >= 4; off >>= 1)
        #pragma unroll
        for (int nt = 0; nt < 4; nt++){
            s[nt][0] += __shfl_xor_sync(0xffffffff, s[nt][0], off);
            s[nt][1] += __shfl_xor_sync(0xffffffff, s[nt][1], off);
        }
    if (qrow == 0){
        #pragma unroll
        for (int nt = 0; nt < 4; nt++){
            int j = n0 + nt*8 + qk2;
            float v0 = s[nt][0] * (1.0f/256.0f);
            float v1 = s[nt][1] * (1.0f/256.0f);
            gbuf[j] = v0; gbuf[j+1] = v1;
            g_gctx[b*DM + j]     = v0;
            g_gctx[b*DM + j + 1] = v1;
        }
    }
    __syncthreads();

    // router on warp 0
    if (warp == 0){
        float p[6] = {0,0,0,0,0,0};
        for (int k = lane; k < DM; k += 32){
            float g = gbuf[k];
            const float* w = Wr + k*NE;
            #pragma unroll
            for (int e = 0; e < 6; e++) p[e] = fmaf(g, w[e], p[e]);
        }
        #pragma unroll
        for (int off = 16; off; off >>= 1)
            #pragma unroll
            for (int e = 0; e < 6; e++) p[e] += __shfl_xor_sync(0xffffffff, p[e], off);
        if (lane == 0){
            float l[6], pr[6];
            #pragma unroll
            for (int e = 0; e < 6; e++) l[e] = p[e] + br[e];
            float m = l[0];
            #pragma unroll
            for (int e = 1; e < 6; e++) m = fmaxf(m, l[e]);
            float sv = 0.0f;
            #pragma unroll
            for (int e = 0; e < 6; e++){ pr[e] = expf(l[e] - m); sv += pr[e]; }
            float inv = 1.0f / sv;
            #pragma unroll
            for (int e = 0; e < 6; e++){ pr[e] *= inv; g_probs[b*NE + e] = pr[e]; }
            int pl = phase[b];
            int sel = pl + ((pr[pl+3] > pr[pl]) ? 3 : 0);
            g_sel[b] = sel;
            if (b < 4){
                #pragma unroll
                for (int e = 0; e < 6; e++){
                    int idx = atomicAdd(&g_cnt[e], 1);
                    g_list[e*512 + idx] = b;
                }
            } else {
                int idx = atomicAdd(&g_cnt[sel], 1);
                g_list[sel*512 + idx] = b;
            }
        }
    }
}

// ---------------- K3c: base via bf16 MMA (validated R7) ----------------
__global__ void __launch_bounds__(256, 1)
k_base(const float* __restrict__ b1){
    extern __shared__ char smraw[];
    __nv_bfloat16* As = (__nv_bfloat16*)smraw;   // 32 x 1032
    int* bl = (int*)(As + 32*1032);              // 32

    int e = blockIdx.x, tile = blockIdx.y;
    int n = g_cnt[e], s0 = tile*32;
    if (s0 >= n) return;
    int tid = threadIdx.x;

    if (tid < 32){
        int s = s0 + tid;
        bl[tid] = (s < n) ? g_list[e*512 + s] : g_list[e*512];
    }
    __syncthreads();

    {
        int r = tid >> 3, seg = tid & 7;
        int bb = bl[r];
        const float4* src = (const float4*)((seg < 4)
            ? (g_gctx + bb*512 + seg*128)
            : (g_temb + bb*512 + seg*128 - 512));
        __nv_bfloat16* dst = As + r*1032 + seg*128;
        #pragma unroll
        for (int i = 0; i < 32; i++){
            float4 v = src[i];
            *(__nv_bfloat162*)(dst + i*4    ) = __floats2bfloat162_rn(v.x, v.y);
            *(__nv_bfloat162*)(dst + i*4 + 2) = __floats2bfloat162_rn(v.z, v.w);
        }
    }
    __syncthreads();

    int warp = tid >> 5, lane = tid & 31;
    int qrow = lane >> 2;
    int qk2 = (lane & 3) * 2;
    int nb = warp * 64;
    const __nv_bfloat16* W1bE = c_W1b + (size_t)e*512*1024;

    float acc[2][8][4];
    #pragma unroll
    for (int mt = 0; mt < 2; mt++)
        #pragma unroll
        for (int nt = 0; nt < 8; nt++)
            #pragma unroll
            for (int r = 0; r < 4; r++) acc[mt][nt][r] = 0.0f;

    for (int kc = 0; kc < 16; kc++){
        #pragma unroll
        for (int ks = 0; ks < 4; ks++){
            int kof = kc*64 + ks*16 + qk2;
            unsigned a[2][4];
            #pragma unroll
            for (int mt = 0; mt < 2; mt++){
                const __nv_bfloat16* ap = As + (mt*16 + qrow)*1032 + kof;
                a[mt][0] = *(const unsigned*)(ap);
                a[mt][1] = *(const unsigned*)(ap + 8*1032);
                a[mt][2] = *(const unsigned*)(ap + 8);
                a[mt][3] = *(const unsigned*)(ap + 8*1032 + 8);
            }
            #pragma unroll
            for (int nt = 0; nt < 8; nt++){
                const __nv_bfloat16* bp = W1bE + (size_t)(nb + nt*8 + qrow)*1024 + kof;
                unsigned b0 = *(const unsigned*)(bp);
                unsigned b1v = *(const unsigned*)(bp + 8);
                mma16816(acc[0][nt], a[0], b0, b1v);
                mma16816(acc[1][nt], a[1], b0, b1v);
            }
        }
    }

    #pragma unroll
    for (int mt = 0; mt < 2; mt++){
        #pragma unroll
        for (int half = 0; half < 2; half++){
            int r = mt*16 + qrow + half*8;
            if (s0 + r < n){
                int bb = bl[r];
                float* dst = g_base + ((size_t)e*B + bb)*512;
                #pragma unroll
                for (int nt = 0; nt < 8; nt++){
                    int h = nb + nt*8 + qk2;
                    float2 o;
                    o.x = acc[mt][nt][half*2    ] + b1[e*512 + h];
                    o.y = acc[mt][nt][half*2 + 1] + b1[e*512 + h + 1];
                    *(float2*)(dst + h) = o;
                }
            }
        }
    }
}

// ---------------- K4: expert MLP (validated R7) ----------------
__global__ void __launch_bounds__(256, 2)
k_expert(const float* __restrict__ fut, const float* __restrict__ eps,
         const int* __restrict__ t, const float* __restrict__ b2){
    extern __shared__ char smraw[];
    __nv_bfloat16* nzs = (__nv_bfloat16*)smraw;       // 64 x 72
    __nv_bfloat16* hss = nzs + 64*72;                 // 64 x 520
    float* basev = (float*)(hss + 64*520);            // 512
    __shared__ float red[8];

    int p = blockIdx.x;
    int b, e;
    if (p < 24){ b = p / 6; e = p - b*6; }
    else       { b = p - 20; e = g_sel[p - 20]; }
    int tid = threadIdx.x;
    bool do_loss  = (e == g_sel[b]);
    bool do_store = (b < 4);

    float ab = g_ab[t[b]];
    float sa = sqrtf(ab), sb = sqrtf(1.0f - ab);

    {
        int r = tid >> 2, c0 = (tid & 3) * 16;
        const float4* f4 = (const float4*)(fut + (size_t)b*4096 + r*64 + c0);
        const float4* e4 = (const float4*)(eps + (size_t)b*4096 + r*64 + c0);
        __nv_bfloat16* dst = nzs + r*72 + c0;
        #pragma unroll
        for (int i = 0; i < 4; i++){
            float4 vf = f4[i], ve = e4[i];
            *(__nv_bfloat162*)(dst + i*4    ) = __floats2bfloat162_rn(fmaf(sa,vf.x,sb*ve.x), fmaf(sa,vf.y,sb*ve.y));
            *(__nv_bfloat162*)(dst + i*4 + 2) = __floats2bfloat162_rn(fmaf(sa,vf.z,sb*ve.z), fmaf(sa,vf.w,sb*ve.w));
        }
    }
    basev[tid]       = g_base[((size_t)e*B + b)*512 + tid];
    basev[tid + 256] = g_base[((size_t)e*B + b)*512 + tid + 256];
    __syncthreads();

    int warp = tid >> 5, lane = tid & 31;
    int qrow = lane >> 2, qk2 = (lane & 3) * 2;

    {
        int n0 = warp * 64;
        const __nv_bfloat16* W1nE = c_W1n + (size_t)e*512*64;

        unsigned a[4][4][4];
        #pragma unroll
        for (int mt = 0; mt < 4; mt++)
            #pragma unroll
            for (int ks = 0; ks < 4; ks++){
                const __nv_bfloat16* ap = nzs + (mt*16 + qrow)*72 + ks*16 + qk2;
                a[mt][ks][0] = *(const unsigned*)(ap);
                a[mt][ks][1] = *(const unsigned*)(ap + 8*72);
                a[mt][ks][2] = *(const unsigned*)(ap + 8);
                a[mt][ks][3] = *(const unsigned*)(ap + 8*72 + 8);
            }

        #pragma unroll
        for (int nto = 0; nto < 8; nto++){
            int h8 = n0 + nto*8;
            unsigned bfr[4][2];
            #pragma unroll
            for (int ks = 0; ks < 4; ks++){
                const __nv_bfloat16* bp = W1nE + (h8 + qrow)*64 + ks*16 + qk2;
                bfr[ks][0] = *(const unsigned*)(bp);
                bfr[ks][1] = *(const unsigned*)(bp + 8);
            }
            float c0v[4][4];
            #pragma unroll
            for (int mt = 0; mt < 4; mt++)
                #pragma unroll
                for (int r = 0; r < 4; r++) c0v[mt][r] = 0.0f;
            #pragma unroll
            for (int ks = 0; ks < 4; ks++){
                #pragma unroll
                for (int mt = 0; mt < 4; mt++)
                    mma16816(c0v[mt], a[mt][ks], bfr[ks][0], bfr[ks][1]);
            }
            int h = h8 + qk2;
            float ba0 = basev[h], ba1 = basev[h+1];
            #pragma unroll
            for (int mt = 0; mt < 4; mt++){
                int r = mt*16 + qrow;
                *(__nv_bfloat162*)(hss + r*520 + h) =
                    __floats2bfloat162_rn(gelu_fast(c0v[mt][0] + ba0), gelu_fast(c0v[mt][1] + ba1));
                *(__nv_bfloat162*)(hss + (r+8)*520 + h) =
                    __floats2bfloat162_rn(gelu_fast(c0v[mt][2] + ba0), gelu_fast(c0v[mt][3] + ba1));
            }
        }
    }
    __syncthreads();

    int f0 = warp * 8;
    const __nv_bfloat16* W2tE = c_W2t + (size_t)e*64*512;

    float acc[4][4];
    #pragma unroll
    for (int mt = 0; mt < 4; mt++)
        #pragma unroll
        for (int r = 0; r < 4; r++) acc[mt][r] = 0.0f;

    #pragma unroll 8
    for (int ks = 0; ks < 32; ks++){
        const __nv_bfloat16* bp = W2tE + (f0 + qrow)*512 + ks*16 + qk2;
        unsigned b0 = *(const unsigned*)(bp);
        unsigned b1v = *(const unsigned*)(bp + 8);
        #pragma unroll
        for (int mt = 0; mt < 4; mt++){
            const __nv_bfloat16* ap = hss + (mt*16 + qrow)*520 + ks*16 + qk2;
            unsigned a2[4];
            a2[0] = *(const unsigned*)(ap);
            a2[1] = *(const unsigned*)(ap + 8*520);
            a2[2] = *(const unsigned*)(ap + 8);
            a2[3] = *(const unsigned*)(ap + 8*520 + 8);
            mma16816(acc[mt], a2, b0, b1v);
        }
    }

    float lsum = 0.0f;
    int fcol = f0 + qk2;
    float bb0 = b2[e*64 + fcol], bb1 = b2[e*64 + fcol + 1];
    #pragma unroll
    for (int mt = 0; mt < 4; mt++){
        #pragma unroll
        for (int half = 0; half < 2; half++){
            int r = mt*16 + qrow + half*8;
            float o0 = acc[mt][half*2    ] + bb0;
            float o1 = acc[mt][half*2 + 1] + bb1;
            if (do_store){
                float2 st; st.x = o0; st.y = o1;
                *(float2*)&g_outsub[((e*4 + b)*64 + r)*64 + fcol] = st;
            }
            if (do_loss){
                float2 ev = *(const float2*)&eps[(size_t)b*4096 + r*64 + fcol];
                float d0 = o0 - ev.x, d1 = o1 - ev.y;
                lsum += d0*d0 + d1*d1;
            }
        }
    }

    if (do_loss){
        #pragma unroll
        for (int off = 16; off; off >>= 1) lsum += __shfl_xor_sync(0xffffffff, lsum, off);
        if (lane == 0) red[warp] = lsum;
        __syncthreads();
        if (tid == 0){
            float tot = 0.0f;
            #pragma unroll
            for (int w = 0; w < 8; w++) tot += red[w];
            g_loss[b] = tot * (1.0f/4096.0f);
        }
    }
}

// ---------------- K5a ----------------
#define FIN_BLKS 96
__global__ void k_final_partial(){
    int bid = blockIdx.x, tid = threadIdx.x;
    if (bid < 2){
        __shared__ float sh[13];
        if (tid < 13) sh[tid] = 0.0f;
        __syncthreads();
        const float PW[3] = {1.0f, 5.0f, 5.0f};
        int b = bid*256 + tid;
        int s = g_sel[b];
        atomicAdd(&sh[0], g_loss[b] * PW[s % 3]);
        atomicAdd(&sh[1 + s], 1.0f);
        #pragma unroll
        for (int e = 0; e < 6; e++) atomicAdd(&sh[7 + e], g_probs[b*NE + e]);
        __syncthreads();
        if (tid == 0) atomicAdd(&g_accL, sh[0]);
        if (tid < 6){
            atomicAdd(&g_cntF[tid],  sh[1 + tid]);
            atomicAdd(&g_psumE[tid], sh[7 + tid]);
        }
    } else {
        int nb = FIN_BLKS - 2;
        int idx0 = (bid - 2)*256 + tid;
        int stride = nb*256;
        const int pa[7] = {0,1,3,4,0,1,2};
        const int pb[7] = {1,2,4,5,3,4,5};
        float ch = 0.0f;
        for (int i = idx0; i < 16384; i += stride){
            #pragma unroll
            for (int q = 0; q < 7; q++){
                float d = g_outsub[pa[q]*16384 + i] - g_outsub[pb[q]*16384 + i];
                ch += d*d;
            }
        }
        float smv = 0.0f;
        for (int i = idx0; i < 96768; i += stride){
            int e  = i / 16128; int r  = i - e*16128;
            int s  = r / 4032;  int r2 = r - s*4032;
            int idx = (e*4 + s)*4096 + r2;
            float d = g_outsub[idx + 64] - g_outsub[idx];
            smv += d*d;
        }
        #pragma unroll
        for (int off = 16; off; off >>= 1){
            ch  += __shfl_xor_sync(0xffffffff, ch,  off);
            smv += __shfl_xor_sync(0xffffffff, smv, off);
        }
        if ((tid & 31) == 0){
            atomicAdd(&g_accC, ch);
            atomicAdd(&g_accS, smv);
        }
    }
}

// ---------------- K5b ----------------
__global__ void k_final_sum(float* __restrict__ out){
    if (threadIdx.x == 0){
        float lb = 0.0f;
        #pragma unroll
        for (int e = 0; e < 6; e++)
            lb += (g_cntF[e] / 512.0f) * (g_psumE[e] / 512.0f);
        out[0] = g_accL / 512.0f
               + 0.01f * (g_accC / 16384.0f + 0.5f * g_accS / 16128.0f)
               + 0.06f * lb;
    }
}

// ---------------- launch ----------------
extern "C" void kernel_launch(void* const* d_in, const int* in_sizes, int n_in,
                              void* d_out, int out_size){
    const float* obs  = (const float*)d_in[0];
    const float* fut  = (const float*)d_in[1];
    const float* sc   = (const float*)d_in[2];
    const float* eps  = (const float*)d_in[3];
    const int*   phase= (const int*)  d_in[4];
    const int*   t    = (const int*)  d_in[5];
    const float* Wenc = (const float*)d_in[6];
    const float* benc = (const float*)d_in[7];
    const float* Wstat= (const float*)d_in[8];
    const float* Wr   = (const float*)d_in[9];
    const float* br   = (const float*)d_in[10];
    const float* W1   = (const float*)d_in[11];
    const float* b1   = (const float*)d_in[12];
    const float* W2   = (const float*)d_in[13];
    const float* b2   = (const float*)d_in[14];

    const int SMEM_CTX  = 256*APAD*2 + 2*512*4;         // 40,960 B
    const int SMEM_BASE = 32*1032*2 + 128;
    const int SMEM_EXP  = (64*72 + 64*520)*2 + 512*4;   // 77,824 B

    static bool once = false;
    static cudaStream_t s2;
    static cudaEvent_t evFork, evJoin;
    if (!once){
        cudaFuncSetAttribute(k_ctx_fused, cudaFuncAttributeMaxDynamicSharedMemorySize, SMEM_CTX);
        cudaFuncSetAttribute(k_base,      cudaFuncAttributeMaxDynamicSharedMemorySize, SMEM_BASE);
        cudaFuncSetAttribute(k_expert,    cudaFuncAttributeMaxDynamicSharedMemorySize, SMEM_EXP);
        cudaStreamCreateWithFlags(&s2, cudaStreamNonBlocking);
        cudaEventCreateWithFlags(&evFork, cudaEventDisableTiming);
        cudaEventCreateWithFlags(&evJoin, cudaEventDisableTiming);
        once = true;
    }

    // init + wenc convert must precede ctx (list atomics + B operand)
    k_init        <<<1, 32>>>();
    k_convert_wenc<<<4, 256>>>(Wenc);

    cudaEventRecord(evFork, 0);
    cudaStreamWaitEvent(s2, evFork, 0);
    k_temb      <<<B, 256, 0, s2>>>(t);
    k_convert_w1<<<dim3(16, 34, NE), 256, 0, s2>>>(W1);
    k_convert_w2<<<dim3(2, 16, NE), 256, 0, s2>>>(W2);
    cudaEventRecord(evJoin, s2);

    k_ctx_fused <<<B, 512, SMEM_CTX>>>(obs, sc, benc, Wstat, Wr, br, phase);

    cudaStreamWaitEvent(0, evJoin, 0);

    k_base         <<<dim3(NE, 16), 256, SMEM_BASE>>>(b1);
    k_expert       <<<NPAIR, 256, SMEM_EXP>>>(fut, eps, t, b2);
    k_final_partial<<<FIN_BLKS, 256>>>();
    k_final_sum    <<<1, 32>>>((float*)d_out);
}

// round 9
// speedup vs baseline: 3.4806x; 1.0983x over previous
#include <cuda_runtime.h>
#include <cuda_bf16.h>
#include <math.h>

#define B   512
#define TP  256
#define DM  512
#define DS  32
#define NE  6
#define NPAIR 532

// ---------------- device scratch ----------------
__device__ float g_ab[1000];
__device__ float g_gctx[B*DM];
__device__ float g_temb[B*DM];
__device__ float g_probs[B*NE];
__device__ int   g_sel[B];
__device__ float g_loss[B];
__device__ float g_outsub[NE*4*64*64];
__device__ int   g_cnt[NE];
__device__ int   g_list[NE*512];
__device__ float g_base[NE*B*512];
__device__ __nv_bfloat16 c_Wenc[DM*64];
__device__ __nv_bfloat16 c_W1n[NE*512*64];
__device__ __nv_bfloat16 c_W1b[(size_t)NE*512*1024];
__device__ __nv_bfloat16 c_W2t[NE*64*512];
__device__ float g_accL, g_accC, g_accS;
__device__ float g_psumE[NE];
__device__ float g_cntF[NE];
__device__ unsigned g_finDone;

__device__ __forceinline__ float gelu_fast(float x){
    float s = x*x;
    float p = x * fmaf(s, 0.044715f, 1.0f);
    float argv = p * -2.3022083f;
    float e;
    asm("ex2.approx.f32 %0, %1;" : "=f"(e) : "f"(argv));
    float r;
    asm("rcp.approx.f32 %0, %1;" : "=f"(r) : "f"(e + 1.0f));
    return x * r;
}

__device__ __forceinline__ void mma16816(float* c, const unsigned* a, unsigned b0, unsigned b1){
    asm("mma.sync.aligned.m16n8k16.row.col.f32.bf16.bf16.f32 "
        "{%0,%1,%2,%3}, {%4,%5,%6,%7}, {%8,%9}, {%0,%1,%2,%3};"
        : "+f"(c[0]), "+f"(c[1]), "+f"(c[2]), "+f"(c[3])
        : "r"(a[0]), "r"(a[1]), "r"(a[2]), "r"(a[3]), "r"(b0), "r"(b1));
}

// ---------------- K0: init scalars + Wenc convert ----------------
__global__ void k_init2(const float* __restrict__ Wenc){
    int tid = threadIdx.x;
    if (blockIdx.x == 0){
        if (tid < NE){ g_cnt[tid] = 0; g_psumE[tid] = 0.0f; g_cntF[tid] = 0.0f; }
        if (tid == 6){ g_accL = 0.0f; g_accC = 0.0f; g_accS = 0.0f; g_finDone = 0u; }
        g_loss[tid] = 0.0f;
        g_loss[tid + 256] = 0.0f;
        if (tid == 0){
            float ab = 1.0f;
            const float step = (0.02f - 0.0001f) / 999.0f;
            for (int i = 0; i < 1000; i++){
                float beta = 0.0001f + step * (float)i;
                ab *= (1.0f - beta);
                g_ab[i] = ab;
            }
        }
    } else {
        int gid = (blockIdx.x - 1)*256 + tid;    // 1024 threads
        int n = gid >> 1, kh = (gid & 1) * 32;
        #pragma unroll
        for (int i = 0; i < 32; i++){
            int k = kh + i;
            c_Wenc[n*64 + k] = __float2bfloat16_rn(Wenc[k*DM + n]);
        }
    }
}

// ---------------- K1: merged prep (W1, W2 converts + temb) ----------------
__global__ void k_prep(const int* __restrict__ t,
                       const float* __restrict__ W1, const float* __restrict__ W2){
    __shared__ float sm[32][33];
    int bid = blockIdx.x;
    int tid = threadIdx.x;

    if (bid < 3264){                       // W1 convert: e*544 tiles
        int e = bid / 544, rem = bid - e*544;
        int kt = rem >> 4, ht = rem & 15;
        int i = tid >> 3, j4 = (tid & 7) * 4;
        float4 v = *(const float4*)&W1[((size_t)e*1088 + kt*32 + i)*512 + ht*32 + j4];
        sm[i][j4] = v.x; sm[i][j4+1] = v.y; sm[i][j4+2] = v.z; sm[i][j4+3] = v.w;
        __syncthreads();
        int h = ht*32 + i;
        int k = kt*32 + j4;
        __nv_bfloat162 p0 = __floats2bfloat162_rn(sm[j4][i],   sm[j4+1][i]);
        __nv_bfloat162 p1 = __floats2bfloat162_rn(sm[j4+2][i], sm[j4+3][i]);
        __nv_bfloat16* dst;
        if (kt < 2) dst = c_W1n + ((size_t)e*512 + h)*64 + k;
        else        dst = c_W1b + ((size_t)e*512 + h)*1024 + (k - 64);
        *(__nv_bfloat162*)dst       = p0;
        *(__nv_bfloat162*)(dst + 2) = p1;
    } else if (bid < 3456){                // W2 convert
        int idx2 = bid - 3264;
        int e = idx2 >> 5, rem = idx2 & 31;
        int ht = rem >> 1, ft = rem & 1;
        int i = tid >> 3, j4 = (tid & 7) * 4;
        float4 v = *(const float4*)&W2[((size_t)e*512 + ht*32 + i)*64 + ft*32 + j4];
        sm[i][j4] = v.x; sm[i][j4+1] = v.y; sm[i][j4+2] = v.z; sm[i][j4+3] = v.w;
        __syncthreads();
        int f = ft*32 + i;
        int h = ht*32 + j4;
        __nv_bfloat162 p0 = __floats2bfloat162_rn(sm[j4][i],   sm[j4+1][i]);
        __nv_bfloat162 p1 = __floats2bfloat162_rn(sm[j4+2][i], sm[j4+3][i]);
        __nv_bfloat16* dst = c_W2t + ((size_t)e*64 + f)*512 + h;
        *(__nv_bfloat162*)dst       = p0;
        *(__nv_bfloat162*)(dst + 2) = p1;
    } else {                               // temb
        int b = bid - 3456;
        float tv = (float)t[b];
        for (int j = tid; j < DM; j += 256){
            int i = (j < 256) ? j : (j - 256);
            float freq = expf(-9.210340371976184f * (float)i / 256.0f);
            float a = tv * freq;
            g_temb[b*DM + j] = (j < 256) ? sinf(a) : cosf(a);
        }
    }
}

// ---------------- K2: fused ctx GEMM + router (validated R8) ----------------
#define APAD 72
__global__ void __launch_bounds__(512, 1)
k_ctx_fused(const float* __restrict__ obs, const float* __restrict__ sc,
            const float* __restrict__ benc, const float* __restrict__ Wstat,
            const float* __restrict__ Wr, const float* __restrict__ br,
            const int* __restrict__ phase){
    extern __shared__ char smraw[];
    __nv_bfloat16* As = (__nv_bfloat16*)smraw;     // 256 x 72 bf16
    float* pre  = (float*)(As + 256*APAD);          // 512
    float* gbuf = pre + 512;                        // 512

    int b = blockIdx.x;
    int tid = threadIdx.x;

    {
        int row = tid >> 1;
        int c0  = (tid & 1) * 32;
        const float4* src = (const float4*)(obs + (size_t)b*TP*64 + row*64 + c0);
        __nv_bfloat16* arow = As + row*APAD + c0;
        #pragma unroll
        for (int i = 0; i < 8; i++){
            float4 v = src[i];
            *(__nv_bfloat162*)(arow + i*4    ) = __floats2bfloat162_rn(v.x, v.y);
            *(__nv_bfloat162*)(arow + i*4 + 2) = __floats2bfloat162_rn(v.z, v.w);
        }
    }
    {
        float acc = benc[tid];
        #pragma unroll
        for (int k = 0; k < 32; k++) acc = fmaf(sc[b*DS + k], Wstat[k*DM + tid], acc);
        pre[tid] = acc;
    }
    __syncthreads();

    int warp = tid >> 5, lane = tid & 31;
    int qrow = lane >> 2, qk2 = (lane & 3) * 2;
    int n0 = warp * 32;

    unsigned bfr[4][4][2];
    #pragma unroll
    for (int nt = 0; nt < 4; nt++)
        #pragma unroll
        for (int ks = 0; ks < 4; ks++){
            const __nv_bfloat16* bp = c_Wenc + (n0 + nt*8 + qrow)*64 + ks*16 + qk2;
            bfr[nt][ks][0] = *(const unsigned*)(bp);
            bfr[nt][ks][1] = *(const unsigned*)(bp + 8);
        }
    float prev[4][2];
    #pragma unroll
    for (int nt = 0; nt < 4; nt++){
        prev[nt][0] = pre[n0 + nt*8 + qk2];
        prev[nt][1] = pre[n0 + nt*8 + qk2 + 1];
    }

    float s[4][2];
    #pragma unroll
    for (int nt = 0; nt < 4; nt++){ s[nt][0] = 0.0f; s[nt][1] = 0.0f; }

    #pragma unroll 2
    for (int mc = 0; mc < 8; mc++){
        unsigned a[2][4][4];
        #pragma unroll
        for (int mt = 0; mt < 2; mt++)
            #pragma unroll
            for (int ks = 0; ks < 4; ks++){
                const __nv_bfloat16* ap = As + (mc*32 + mt*16 + qrow)*APAD + ks*16 + qk2;
                a[mt][ks][0] = *(const unsigned*)(ap);
                a[mt][ks][1] = *(const unsigned*)(ap + 8*APAD);
                a[mt][ks][2] = *(const unsigned*)(ap + 8);
                a[mt][ks][3] = *(const unsigned*)(ap + 8*APAD + 8);
            }
        float c[2][4][4];
        #pragma unroll
        for (int mt = 0; mt < 2; mt++)
            #pragma unroll
            for (int nt = 0; nt < 4; nt++)
                #pragma unroll
                for (int r = 0; r < 4; r++) c[mt][nt][r] = 0.0f;
        #pragma unroll
        for (int ks = 0; ks < 4; ks++)
            #pragma unroll
            for (int mt = 0; mt < 2; mt++)
                #pragma unroll
                for (int nt = 0; nt < 4; nt++)
                    mma16816(c[mt][nt], a[mt][ks], bfr[nt][ks][0], bfr[nt][ks][1]);
        #pragma unroll
        for (int mt = 0; mt < 2; mt++)
            #pragma unroll
            for (int nt = 0; nt < 4; nt++){
                s[nt][0] += gelu_fast(c[mt][nt][0] + prev[nt][0]) + gelu_fast(c[mt][nt][2] + prev[nt][0]);
                s[nt][1] += gelu_fast(c[mt][nt][1] + prev[nt][1]) + gelu_fast(c[mt][nt][3] + prev[nt][1]);
            }
    }

    #pragma unroll
    for (int off = 16; off >= 4; off >>= 1)
        #pragma unroll
        for (int nt = 0; nt < 4; nt++){
            s[nt][0] += __shfl_xor_sync(0xffffffff, s[nt][0], off);
            s[nt][1] += __shfl_xor_sync(0xffffffff, s[nt][1], off);
        }
    if (qrow == 0){
        #pragma unroll
        for (int nt = 0; nt < 4; nt++){
            int j = n0 + nt*8 + qk2;
            float v0 = s[nt][0] * (1.0f/256.0f);
            float v1 = s[nt][1] * (1.0f/256.0f);
            gbuf[j] = v0; gbuf[j+1] = v1;
            g_gctx[b*DM + j]     = v0;
            g_gctx[b*DM + j + 1] = v1;
        }
    }
    __syncthreads();

    if (warp == 0){
        float p[6] = {0,0,0,0,0,0};
        for (int k = lane; k < DM; k += 32){
            float g = gbuf[k];
            const float* w = Wr + k*NE;
            #pragma unroll
            for (int e = 0; e < 6; e++) p[e] = fmaf(g, w[e], p[e]);
        }
        #pragma unroll
        for (int off = 16; off; off >>= 1)
            #pragma unroll
            for (int e = 0; e < 6; e++) p[e] += __shfl_xor_sync(0xffffffff, p[e], off);
        if (lane == 0){
            float l[6], pr[6];
            #pragma unroll
            for (int e = 0; e < 6; e++) l[e] = p[e] + br[e];
            float m = l[0];
            #pragma unroll
            for (int e = 1; e < 6; e++) m = fmaxf(m, l[e]);
            float sv = 0.0f;
            #pragma unroll
            for (int e = 0; e < 6; e++){ pr[e] = expf(l[e] - m); sv += pr[e]; }
            float inv = 1.0f / sv;
            #pragma unroll
            for (int e = 0; e < 6; e++){ pr[e] *= inv; g_probs[b*NE + e] = pr[e]; }
            int pl = phase[b];
            int sel = pl + ((pr[pl+3] > pr[pl]) ? 3 : 0);
            g_sel[b] = sel;
            if (b < 4){
                #pragma unroll
                for (int e = 0; e < 6; e++){
                    int idx = atomicAdd(&g_cnt[e], 1);
                    g_list[e*512 + idx] = b;
                }
            } else {
                int idx = atomicAdd(&g_cnt[sel], 1);
                g_list[sel*512 + idx] = b;
            }
        }
    }
}

// ---------------- K3c: base via bf16 MMA, h-split over grid.z ----------------
__global__ void __launch_bounds__(256, 1)
k_base(const float* __restrict__ b1){
    extern __shared__ char smraw[];
    __nv_bfloat16* As = (__nv_bfloat16*)smraw;   // 32 x 1032
    int* bl = (int*)(As + 32*1032);              // 32

    int e = blockIdx.x, tile = blockIdx.y;
    int n = g_cnt[e], s0 = tile*32;
    if (s0 >= n) return;
    int tid = threadIdx.x;

    if (tid < 32){
        int s = s0 + tid;
        bl[tid] = (s < n) ? g_list[e*512 + s] : g_list[e*512];
    }
    __syncthreads();

    {
        int r = tid >> 3, seg = tid & 7;
        int bb = bl[r];
        const float4* src = (const float4*)((seg < 4)
            ? (g_gctx + bb*512 + seg*128)
            : (g_temb + bb*512 + seg*128 - 512));
        __nv_bfloat16* dst = As + r*1032 + seg*128;
        #pragma unroll
        for (int i = 0; i < 32; i++){
            float4 v = src[i];
            *(__nv_bfloat162*)(dst + i*4    ) = __floats2bfloat162_rn(v.x, v.y);
            *(__nv_bfloat162*)(dst + i*4 + 2) = __floats2bfloat162_rn(v.z, v.w);
        }
    }
    __syncthreads();

    int warp = tid >> 5, lane = tid & 31;
    int qrow = lane >> 2;
    int qk2 = (lane & 3) * 2;
    int nb = warp * 32 + blockIdx.z * 256;
    const __nv_bfloat16* W1bE = c_W1b + (size_t)e*512*1024;

    float acc[2][4][4];
    #pragma unroll
    for (int mt = 0; mt < 2; mt++)
        #pragma unroll
        for (int nt = 0; nt < 4; nt++)
            #pragma unroll
            for (int r = 0; r < 4; r++) acc[mt][nt][r] = 0.0f;

    for (int kc = 0; kc < 16; kc++){
        #pragma unroll
        for (int ks = 0; ks < 4; ks++){
            int kof = kc*64 + ks*16 + qk2;
            unsigned a[2][4];
            #pragma unroll
            for (int mt = 0; mt < 2; mt++){
                const __nv_bfloat16* ap = As + (mt*16 + qrow)*1032 + kof;
                a[mt][0] = *(const unsigned*)(ap);
                a[mt][1] = *(const unsigned*)(ap + 8*1032);
                a[mt][2] = *(const unsigned*)(ap + 8);
                a[mt][3] = *(const unsigned*)(ap + 8*1032 + 8);
            }
            #pragma unroll
            for (int nt = 0; nt < 4; nt++){
                const __nv_bfloat16* bp = W1bE + (size_t)(nb + nt*8 + qrow)*1024 + kof;
                unsigned b0 = *(const unsigned*)(bp);
                unsigned b1v = *(const unsigned*)(bp + 8);
                mma16816(acc[0][nt], a[0], b0, b1v);
                mma16816(acc[1][nt], a[1], b0, b1v);
            }
        }
    }

    #pragma unroll
    for (int mt = 0; mt < 2; mt++){
        #pragma unroll
        for (int half = 0; half < 2; half++){
            int r = mt*16 + qrow + half*8;
            if (s0 + r < n){
                int bb = bl[r];
                float* dst = g_base + ((size_t)e*B + bb)*512;
                #pragma unroll
                for (int nt = 0; nt < 4; nt++){
                    int h = nb + nt*8 + qk2;
                    float2 o;
                    o.x = acc[mt][nt][half*2    ] + b1[e*512 + h];
                    o.y = acc[mt][nt][half*2 + 1] + b1[e*512 + h + 1];
                    *(float2*)(dst + h) = o;
                }
            }
        }
    }
}

// ---------------- K4: expert MLP, M-split halves, 128 threads, 5 blocks/SM ----------------
__global__ void __launch_bounds__(128, 5)
k_expert(const float* __restrict__ fut, const float* __restrict__ eps,
         const int* __restrict__ t, const float* __restrict__ b2){
    extern __shared__ char smraw[];
    __nv_bfloat16* nzs = (__nv_bfloat16*)smraw;       // 32 x 72
    __nv_bfloat16* hss = nzs + 32*72;                 // 32 x 520
    float* basev = (float*)(hss + 32*520);            // 512
    __shared__ float red[4];

    int p2 = blockIdx.x;
    int p = p2 >> 1, mhalf = p2 & 1;
    int b, e;
    if (p < 24){ b = p / 6; e = p - b*6; }
    else       { b = p - 20; e = g_sel[p - 20]; }
    int tid = threadIdx.x;
    bool do_loss  = (e == g_sel[b]);
    bool do_store = (b < 4);

    float ab = g_ab[t[b]];
    float sa = sqrtf(ab), sb = sqrtf(1.0f - ab);

    {   // nzs = bf16(noisy) rows [mhalf*32, mhalf*32+32)
        int r = tid >> 2, c0 = (tid & 3) * 16;
        int gr = mhalf*32 + r;
        const float4* f4 = (const float4*)(fut + (size_t)b*4096 + gr*64 + c0);
        const float4* e4 = (const float4*)(eps + (size_t)b*4096 + gr*64 + c0);
        __nv_bfloat16* dst = nzs + r*72 + c0;
        #pragma unroll
        for (int i = 0; i < 4; i++){
            float4 vf = f4[i], ve = e4[i];
            *(__nv_bfloat162*)(dst + i*4    ) = __floats2bfloat162_rn(fmaf(sa,vf.x,sb*ve.x), fmaf(sa,vf.y,sb*ve.y));
            *(__nv_bfloat162*)(dst + i*4 + 2) = __floats2bfloat162_rn(fmaf(sa,vf.z,sb*ve.z), fmaf(sa,vf.w,sb*ve.w));
        }
    }
    #pragma unroll
    for (int i = 0; i < 4; i++)
        basev[tid + i*128] = g_base[((size_t)e*B + b)*512 + tid + i*128];
    __syncthreads();

    int warp = tid >> 5, lane = tid & 31;
    int qrow = lane >> 2, qk2 = (lane & 3) * 2;

    // ---- phase1: warp owns 128 h-cols, M=32 local ----
    {
        int n0 = warp * 128;
        const __nv_bfloat16* W1nE = c_W1n + (size_t)e*512*64;

        unsigned a[2][4][4];
        #pragma unroll
        for (int mt = 0; mt < 2; mt++)
            #pragma unroll
            for (int ks = 0; ks < 4; ks++){
                const __nv_bfloat16* ap = nzs + (mt*16 + qrow)*72 + ks*16 + qk2;
                a[mt][ks][0] = *(const unsigned*)(ap);
                a[mt][ks][1] = *(const unsigned*)(ap + 8*72);
                a[mt][ks][2] = *(const unsigned*)(ap + 8);
                a[mt][ks][3] = *(const unsigned*)(ap + 8*72 + 8);
            }

        #pragma unroll 4
        for (int nto = 0; nto < 16; nto++){
            int h8 = n0 + nto*8;
            unsigned bfr[4][2];
            #pragma unroll
            for (int ks = 0; ks < 4; ks++){
                const __nv_bfloat16* bp = W1nE + (h8 + qrow)*64 + ks*16 + qk2;
                bfr[ks][0] = *(const unsigned*)(bp);
                bfr[ks][1] = *(const unsigned*)(bp + 8);
            }
            float c0v[2][4];
            #pragma unroll
            for (int mt = 0; mt < 2; mt++)
                #pragma unroll
                for (int r = 0; r < 4; r++) c0v[mt][r] = 0.0f;
            #pragma unroll
            for (int ks = 0; ks < 4; ks++){
                #pragma unroll
                for (int mt = 0; mt < 2; mt++)
                    mma16816(c0v[mt], a[mt][ks], bfr[ks][0], bfr[ks][1]);
            }
            int h = h8 + qk2;
            float ba0 = basev[h], ba1 = basev[h+1];
            #pragma unroll
            for (int mt = 0; mt < 2; mt++){
                int r = mt*16 + qrow;
                *(__nv_bfloat162*)(hss + r*520 + h) =
                    __floats2bfloat162_rn(gelu_fast(c0v[mt][0] + ba0), gelu_fast(c0v[mt][1] + ba1));
                *(__nv_bfloat162*)(hss + (r+8)*520 + h) =
                    __floats2bfloat162_rn(gelu_fast(c0v[mt][2] + ba0), gelu_fast(c0v[mt][3] + ba1));
            }
        }
    }
    __syncthreads();

    // ---- phase2: warp owns 16 f-cols, M=32 local, K=512 ----
    int f0 = warp * 16;
    const __nv_bfloat16* W2tE = c_W2t + (size_t)e*64*512;

    float acc[2][2][4];
    #pragma unroll
    for (int mt = 0; mt < 2; mt++)
        #pragma unroll
        for (int nt = 0; nt < 2; nt++)
            #pragma unroll
            for (int r = 0; r < 4; r++) acc[mt][nt][r] = 0.0f;

    #pragma unroll 8
    for (int ks = 0; ks < 32; ks++){
        unsigned bfr[2][2];
        #pragma unroll
        for (int nt = 0; nt < 2; nt++){
            const __nv_bfloat16* bp = W2tE + (f0 + nt*8 + qrow)*512 + ks*16 + qk2;
            bfr[nt][0] = *(const unsigned*)(bp);
            bfr[nt][1] = *(const unsigned*)(bp + 8);
        }
        #pragma unroll
        for (int mt = 0; mt < 2; mt++){
            const __nv_bfloat16* ap = hss + (mt*16 + qrow)*520 + ks*16 + qk2;
            unsigned a2[4];
            a2[0] = *(const unsigned*)(ap);
            a2[1] = *(const unsigned*)(ap + 8*520);
            a2[2] = *(const unsigned*)(ap + 8);
            a2[3] = *(const unsigned*)(ap + 8*520 + 8);
            mma16816(acc[mt][0], a2, bfr[0][0], bfr[0][1]);
            mma16816(acc[mt][1], a2, bfr[1][0], bfr[1][1]);
        }
    }

    float lsum = 0.0f;
    #pragma unroll
    for (int mt = 0; mt < 2; mt++){
        #pragma unroll
        for (int nt = 0; nt < 2; nt++){
            int fcol = f0 + nt*8 + qk2;
            float bb0 = b2[e*64 + fcol], bb1 = b2[e*64 + fcol + 1];
            #pragma unroll
            for (int h2 = 0; h2 < 2; h2++){
                int rg = mhalf*32 + mt*16 + qrow + h2*8;
                float o0 = acc[mt][nt][h2*2    ] + bb0;
                float o1 = acc[mt][nt][h2*2 + 1] + bb1;
                if (do_store){
                    float2 st; st.x = o0; st.y = o1;
                    *(float2*)&g_outsub[((e*4 + b)*64 + rg)*64 + fcol] = st;
                }
                if (do_loss){
                    float2 ev = *(const float2*)&eps[(size_t)b*4096 + rg*64 + fcol];
                    float d0 = o0 - ev.x, d1 = o1 - ev.y;
                    lsum += d0*d0 + d1*d1;
                }
            }
        }
    }

    if (do_loss){
        #pragma unroll
        for (int off = 16; off; off >>= 1) lsum += __shfl_xor_sync(0xffffffff, lsum, off);
        if (lane == 0) red[warp] = lsum;
        __syncthreads();
        if (tid == 0){
            float tot = red[0] + red[1] + red[2] + red[3];
            atomicAdd(&g_loss[b], tot * (1.0f/4096.0f));
        }
    }
}

// ---------------- K5: parallel final reduction + last-block scalar ----------------
#define FIN_BLKS 96
__global__ void k_final(float* __restrict__ out){
    int bid = blockIdx.x, tid = threadIdx.x;
    if (bid < 2){
        __shared__ float sh[13];
        if (tid < 13) sh[tid] = 0.0f;
        __syncthreads();
        const float PW[3] = {1.0f, 5.0f, 5.0f};
        int b = bid*256 + tid;
        int s = g_sel[b];
        atomicAdd(&sh[0], g_loss[b] * PW[s % 3]);
        atomicAdd(&sh[1 + s], 1.0f);
        #pragma unroll
        for (int e = 0; e < 6; e++) atomicAdd(&sh[7 + e], g_probs[b*NE + e]);
        __syncthreads();
        if (tid == 0) atomicAdd(&g_accL, sh[0]);
        if (tid < 6){
            atomicAdd(&g_cntF[tid],  sh[1 + tid]);
            atomicAdd(&g_psumE[tid], sh[7 + tid]);
        }
    } else {
        int nb = FIN_BLKS - 2;
        int idx0 = (bid - 2)*256 + tid;
        int stride = nb*256;
        const int pa[7] = {0,1,3,4,0,1,2};
        const int pb[7] = {1,2,4,5,3,4,5};
        float ch = 0.0f;
        for (int i = idx0; i < 16384; i += stride){
            #pragma unroll
            for (int q = 0; q < 7; q++){
                float d = g_outsub[pa[q]*16384 + i] - g_outsub[pb[q]*16384 + i];
                ch += d*d;
            }
        }
        float smv = 0.0f;
        for (int i = idx0; i < 96768; i += stride){
            int e  = i / 16128; int r  = i - e*16128;
            int s  = r / 4032;  int r2 = r - s*4032;
            int idx = (e*4 + s)*4096 + r2;
            float d = g_outsub[idx + 64] - g_outsub[idx];
            smv += d*d;
        }
        #pragma unroll
        for (int off = 16; off; off >>= 1){
            ch  += __shfl_xor_sync(0xffffffff, ch,  off);
            smv += __shfl_xor_sync(0xffffffff, smv, off);
        }
        if ((tid & 31) == 0){
            atomicAdd(&g_accC, ch);
            atomicAdd(&g_accS, smv);
        }
    }

    // last block finishes the scalar
    __syncthreads();
    __shared__ bool amLast;
    if (tid == 0){
        __threadfence();
        unsigned old = atomicAdd(&g_finDone, 1u);
        amLast = (old == FIN_BLKS - 1);
    }
    __syncthreads();
    if (amLast && tid == 0){
        __threadfence();
        float lb = 0.0f;
        #pragma unroll
        for (int e = 0; e < 6; e++)
            lb += (g_cntF[e] / 512.0f) * (g_psumE[e] / 512.0f);
        out[0] = g_accL / 512.0f
               + 0.01f * (g_accC / 16384.0f + 0.5f * g_accS / 16128.0f)
               + 0.06f * lb;
    }
}

// ---------------- launch ----------------
extern "C" void kernel_launch(void* const* d_in, const int* in_sizes, int n_in,
                              void* d_out, int out_size){
    const float* obs  = (const float*)d_in[0];
    const float* fut  = (const float*)d_in[1];
    const float* sc   = (const float*)d_in[2];
    const float* eps  = (const float*)d_in[3];
    const int*   phase= (const int*)  d_in[4];
    const int*   t    = (const int*)  d_in[5];
    const float* Wenc = (const float*)d_in[6];
    const float* benc = (const float*)d_in[7];
    const float* Wstat= (const float*)d_in[8];
    const float* Wr   = (const float*)d_in[9];
    const float* br   = (const float*)d_in[10];
    const float* W1   = (const float*)d_in[11];
    const float* b1   = (const float*)d_in[12];
    const float* W2   = (const float*)d_in[13];
    const float* b2   = (const float*)d_in[14];

    const int SMEM_CTX  = 256*APAD*2 + 2*512*4;            // 40,960 B
    const int SMEM_BASE = 32*1032*2 + 128;                 // 66,176 B
    const int SMEM_EXP  = (32*72 + 32*520)*2 + 512*4;      // 39,936 B

    static bool once = false;
    static cudaStream_t s2;
    static cudaEvent_t evFork, evJoin;
    if (!once){
        cudaFuncSetAttribute(k_ctx_fused, cudaFuncAttributeMaxDynamicSharedMemorySize, SMEM_CTX);
        cudaFuncSetAttribute(k_base,      cudaFuncAttributeMaxDynamicSharedMemorySize, SMEM_BASE);
        cudaFuncSetAttribute(k_expert,    cudaFuncAttributeMaxDynamicSharedMemorySize, SMEM_EXP);
        cudaStreamCreateWithFlags(&s2, cudaStreamNonBlocking);
        cudaEventCreateWithFlags(&evFork, cudaEventDisableTiming);
        cudaEventCreateWithFlags(&evJoin, cudaEventDisableTiming);
        once = true;
    }

    k_init2<<<5, 256>>>(Wenc);

    cudaEventRecord(evFork, 0);
    cudaStreamWaitEvent(s2, evFork, 0);
    k_prep<<<3968, 256, 0, s2>>>(t, W1, W2);
    cudaEventRecord(evJoin, s2);

    k_ctx_fused<<<B, 512, SMEM_CTX>>>(obs, sc, benc, Wstat, Wr, br, phase);

    cudaStreamWaitEvent(0, evJoin, 0);

    k_base  <<<dim3(NE, 16, 2), 256, SMEM_BASE>>>(b1);
    k_expert<<<2*NPAIR, 128, SMEM_EXP>>>(fut, eps, t, b2);
    k_final <<<FIN_BLKS, 256>>>((float*)d_out);
}